// round 1
// baseline (speedup 1.0000x reference)
#include <cuda_runtime.h>
#include <math.h>

// Problem constants
#define CUTN    10          // Fock cutoff
#define DMODES  4
#define BATCH   256
#define NLAYERS 4
#define PW      48          // params per layer
#define NBS     48          // total beamsplitter gates (4 layers * 2 interferometers * 6 pairs)
#define NSEC    19          // photon-number sectors 0..18

// ---------------------------------------------------------------------------
// Complex helpers
// ---------------------------------------------------------------------------
__device__ __forceinline__ float2 cmul(float2 a, float2 b) {
    return make_float2(a.x*b.x - a.y*b.y, a.x*b.y + a.y*b.x);
}
__device__ __forceinline__ float2 cfma(float2 a, float2 b, float2 acc) {
    acc.x += a.x*b.x - a.y*b.y;
    acc.y += a.x*b.y + a.y*b.x;
    return acc;
}

// ---------------------------------------------------------------------------
// Device scratch (allocation-free rule: __device__ globals)
// ---------------------------------------------------------------------------
__device__ float2 g_bs[NBS][100][10];      // banded BS gates: [gate][xi*10+xj][t]
__device__ float2 g_sq[16][100];           // squeeze gates [layer*4+mode]
__device__ float2 g_dp[16][100];           // displacement gates [layer*4+mode]
__device__ float2 g_S0[100];               // initial squeezer S0
__device__ float2 g_Dm[BATCH*DMODES][100]; // input displacement matrices
__device__ float2 g_psi[BATCH][DMODES][CUTN]; // per-mode initial vectors

__constant__ int cST[4]  = {1000, 100, 10, 1};
__constant__ int cPI[6]  = {0,0,0,1,1,2};
__constant__ int cPJ[6]  = {1,2,3,2,3,3};

// Weight layout offsets within a layer (P = 48):
// th1:0  ph1:6  vp1:12  rsq:16  th2:20  ph2:26  vp2:32  rd:36  phd:40  kap:44

// ---------------------------------------------------------------------------
// Kernel 1: build all gate matrices via expm (scaling+squaring, Taylor)
// Jobs (one block each):
//   0                 : S0 = expm(-0.25j (a^2 + adag^2))
//   1 .. 1024         : Dm_b = expm(x (adag - a)),  x = inputs[flat]
//   1025 .. 1040      : squeeze (layer l, mode m): expm(0.5 r (a^2 - adag^2))
//   1041 .. 1056      : displacement: expm(al adag - conj(al) a)
//   1057 .. 1968      : BS sector expms -> scattered into banded g_bs
// ---------------------------------------------------------------------------
#define NJOBS (1 + 1024 + 16 + 16 + NBS*NSEC)

__global__ void build_gates(const float* __restrict__ inputs,
                            const float* __restrict__ w)
{
    __shared__ float2 A[100], E[100], P[100], T[100];
    const int job = blockIdx.x;
    const int tid = threadIdx.x;

    int d = CUTN;
    int lo = 0, N = 0, g = 0;
    const bool isBS = (job >= 1057);
    if (isBS) {
        int idx = job - 1057;
        g = idx / NSEC;  N = idx % NSEC;
        lo = max(0, N - (CUTN-1));
        int hi = min(CUTN-1, N);
        d = hi - lo + 1;
    }

    // Build generator into A
    if (tid < d*d) {
        int i = tid / d, j = tid % d;
        float2 v = make_float2(0.f, 0.f);
        if (job == 0) {
            // -0.25j (a^2 + adag^2)
            if (i == j-2)      v = make_float2(0.f, -0.25f * sqrtf((float)(j*(j-1))));
            else if (i == j+2) v = make_float2(0.f, -0.25f * sqrtf((float)((j+1)*(j+2))));
        } else if (job <= 1024) {
            float xv = inputs[job-1];
            if (i == j+1)      v = make_float2( xv * sqrtf((float)(j+1)), 0.f);
            else if (i == j-1) v = make_float2(-xv * sqrtf((float)j),     0.f);
        } else if (job <= 1040) {
            int q = job - 1025; int l = q/4, m = q%4;
            float r = w[l*PW + 16 + m];
            if (i == j-2)      v = make_float2( 0.5f*r*sqrtf((float)(j*(j-1))),       0.f);
            else if (i == j+2) v = make_float2(-0.5f*r*sqrtf((float)((j+1)*(j+2))),   0.f);
        } else if (job <= 1056) {
            int q = job - 1041; int l = q/4, m = q%4;
            float rd = w[l*PW + 36 + m];
            float ph = w[l*PW + 40 + m];
            float ax = rd*cosf(ph), ay = rd*sinf(ph);
            if (i == j+1)      { float s = sqrtf((float)(j+1)); v = make_float2( ax*s,  ay*s); }
            else if (i == j-1) { float s = sqrtf((float)j);     v = make_float2(-ax*s,  ay*s); } // -conj(al)
        } else {
            int l = g / 12; int h = (g % 12) / 6; int p = g % 6;
            float th = w[l*PW + (h ? 20 : 0) + p];
            float ph = w[l*PW + (h ? 26 : 6) + p];
            float cp = cosf(ph), sp = sinf(ph);
            int yi = lo + j; int yj = N - yi;
            if (i == j+1)      { float s = th * sqrtf((float)((yi+1)*yj));   v = make_float2( cp*s,  sp*s); } // t e^{+i ph}
            else if (i == j-1) { float s = th * sqrtf((float)(yi*(yj+1)));   v = make_float2(-cp*s,  sp*s); } // -t e^{-i ph}
        }
        A[tid] = v;
    }
    __syncthreads();

    // expm: M = A/256; E = sum_{k<=8} M^k/k!; then square 8 times
    const float SC = 1.0f/256.0f;
    if (tid < d*d) {
        int i = tid/d, j = tid%d;
        float2 m0 = make_float2(A[tid].x*SC, A[tid].y*SC);
        P[tid] = m0;
        E[tid] = make_float2((i==j ? 1.f : 0.f) + m0.x, m0.y);
    }
    __syncthreads();
    for (int k = 2; k <= 8; ++k) {
        float2 t = make_float2(0.f, 0.f);
        if (tid < d*d) {
            int i = tid/d, j = tid%d;
            for (int u = 0; u < d; ++u)
                t = cfma(P[i*d+u], A[u*d+j], t);
            float f = SC / (float)k;
            t.x *= f; t.y *= f;
        }
        __syncthreads();
        if (tid < d*d) {
            T[tid] = t;
            E[tid].x += t.x; E[tid].y += t.y;
            P[tid] = t;
        }
        __syncthreads();
    }
    for (int s = 0; s < 8; ++s) {
        float2 t = make_float2(0.f, 0.f);
        if (tid < d*d) {
            int i = tid/d, j = tid%d;
            for (int u = 0; u < d; ++u)
                t = cfma(E[i*d+u], E[u*d+j], t);
        }
        __syncthreads();
        if (tid < d*d) E[tid] = t;
        __syncthreads();
    }

    // Writeback
    if (job == 0) {
        if (tid < 100) g_S0[tid] = E[tid];
    } else if (job <= 1024) {
        if (tid < 100) g_Dm[job-1][tid] = E[tid];
    } else if (job <= 1040) {
        if (tid < 100) g_sq[job-1025][tid] = E[tid];
    } else if (job <= 1056) {
        if (tid < 100) g_dp[job-1041][tid] = E[tid];
    } else {
        // Scatter sector into banded layout. Output (xi,xj) with xi+xj=N.
        // banded[.][t] corresponds to input yi = lo+t (t < d), else 0.
        if (tid < d*10) {
            int x = tid/10, t = tid%10;
            int xi = lo + x, xj = N - xi;
            float2 v = (t < d) ? E[x*d + t] : make_float2(0.f, 0.f);
            g_bs[g][xi*10 + xj][t] = v;
        }
    }
}

// ---------------------------------------------------------------------------
// Kernel 2: psi0 = S0[:,0];  g_psi[b][m] = Dm[b*4+m] @ psi0
// ---------------------------------------------------------------------------
__global__ void init_psi()
{
    int t = blockIdx.x * blockDim.x + threadIdx.x;
    if (t >= BATCH*DMODES) return;
    float2 p0[CUTN];
#pragma unroll
    for (int y = 0; y < CUTN; ++y) p0[y] = g_S0[y*CUTN + 0];
    const float2* Dm = g_Dm[t];
#pragma unroll
    for (int i = 0; i < CUTN; ++i) {
        float2 acc = make_float2(0.f, 0.f);
#pragma unroll
        for (int y = 0; y < CUTN; ++y) acc = cfma(Dm[i*CUTN + y], p0[y], acc);
        g_psi[t/DMODES][t%DMODES][i] = acc;
    }
}

// ---------------------------------------------------------------------------
// Persistent circuit kernel: one CTA per batch element, state in SMEM
// ---------------------------------------------------------------------------
__device__ __forceinline__ void apply_bs(float2* S, float2* U, int g, int p, int tid)
{
    // stage banded gate (1000 float2 = 8KB)
    const float2* src = &g_bs[g][0][0];
    for (int q = tid; q < 1000; q += 256) U[q] = src[q];
    __syncthreads();

    const int mi = cPI[p], mj = cPJ[p];
    const int si = cST[mi], sj = cST[mj];
    int sa, sb;
    {
        int r0 = -1, r1 = -1;
        for (int m = 0; m < 4; ++m) {
            if (m == mi || m == mj) continue;
            if (r0 < 0) r0 = m; else r1 = m;
        }
        sa = cST[r0]; sb = cST[r1];
    }
    const int ds = si - sj;

    // 4 phases of 25 slices each: read->regs, sync, write (in-place safe)
    for (int phase = 0; phase < 4; ++phase) {
        float2 acc[10];
        int    oidx[10];
#pragma unroll
        for (int k = 0; k < 10; ++k) {
            int q = k*256 + tid;
            acc[k] = make_float2(0.f, 0.f);
            oidx[k] = -1;
            if (q < 2500) {
                int o  = phase*2500 + q;
                int r  = o / 100;
                int xq = o - r*100;
                int xi = xq / 10, xj = xq - xi*10;
                int N  = xi + xj;
                int lo = max(0, N-9), hi = min(9, N);
                int base = (r/10)*sa + (r%10)*sb;
                int c0 = base + N*sj;
                oidx[k] = c0 + xi*ds;
                const float2* Ur = &U[xq*10];
#pragma unroll
                for (int t = 0; t < 10; ++t) {
                    int yi = min(lo + t, hi);
                    acc[k] = cfma(Ur[t], S[c0 + yi*ds], acc[k]);
                }
            }
        }
        __syncthreads();
#pragma unroll
        for (int k = 0; k < 10; ++k)
            if (oidx[k] >= 0) S[oidx[k]] = acc[k];
        __syncthreads();
    }
}

__device__ __forceinline__ void apply_single(float2* S, float2* U, const float2* Ug, int m, int tid)
{
    for (int q = tid; q < 100; q += 256) U[q] = Ug[q];
    __syncthreads();
    const int sm = cST[m];
    int rs0, rs1, rs2;
    {
        int r[3], c = 0;
        for (int mm = 0; mm < 4; ++mm) if (mm != m) r[c++] = cST[mm];
        rs0 = r[0]; rs1 = r[1]; rs2 = r[2];
    }
    for (int k = 0; k < 4; ++k) {
        int q = k*256 + tid;
        if (q < 1000) {
            int base = (q/100)*rs0 + ((q/10)%10)*rs1 + (q%10)*rs2;
            float2 in[10];
#pragma unroll
            for (int y = 0; y < 10; ++y) in[y] = S[base + y*sm];
#pragma unroll
            for (int x = 0; x < 10; ++x) {
                float2 a = make_float2(0.f, 0.f);
#pragma unroll
                for (int y = 0; y < 10; ++y) a = cfma(U[x*10 + y], in[y], a);
                S[base + x*sm] = a;
            }
        }
    }
    __syncthreads();
}

__device__ __forceinline__ void apply_diag(float2* S, float2* PV, const float* v, bool kerr, int tid)
{
    if (tid < 40) {
        int m = tid / 10, n = tid % 10;
        float ang = v[m] * (kerr ? (float)(n*n) : (float)n);
        PV[tid] = make_float2(cosf(ang), sinf(ang));
    }
    __syncthreads();
    for (int o = tid; o < 10000; o += 256) {
        int i = o/1000, j = (o/100)%10, kk = (o/10)%10, l = o%10;
        float2 ph = cmul(cmul(PV[i], PV[10+j]), cmul(PV[20+kk], PV[30+l]));
        S[o] = cmul(S[o], ph);
    }
    __syncthreads();
}

__global__ void __launch_bounds__(256, 2)
circuit(const float* __restrict__ w, float* __restrict__ out)
{
    extern __shared__ float2 sh[];
    float2* S  = sh;            // 10000
    float2* U  = sh + 10000;    // 1000
    float2* PV = sh + 11000;    // 40
    __shared__ float red[8*4];

    const int b = blockIdx.x, tid = threadIdx.x;

    // initial product state
    if (tid < 40) PV[tid] = g_psi[b][tid/10][tid%10];
    __syncthreads();
    for (int o = tid; o < 10000; o += 256) {
        int i = o/1000, j = (o/100)%10, kk = (o/10)%10, l = o%10;
        S[o] = cmul(cmul(PV[i], PV[10+j]), cmul(PV[20+kk], PV[30+l]));
    }
    __syncthreads();

    for (int lay = 0; lay < NLAYERS; ++lay) {
        const float* wl = w + lay*PW;
        // interferometer 1
        for (int p = 0; p < 6; ++p) apply_bs(S, U, lay*12 + p, p, tid);
        apply_diag(S, PV, wl + 12, false, tid);
        // squeeze
        for (int m = 0; m < 4; ++m) apply_single(S, U, g_sq[lay*4 + m], m, tid);
        // interferometer 2
        for (int p = 0; p < 6; ++p) apply_bs(S, U, lay*12 + 6 + p, p, tid);
        apply_diag(S, PV, wl + 32, false, tid);
        // displacement
        for (int m = 0; m < 4; ++m) apply_single(S, U, g_dp[lay*4 + m], m, tid);
        // Kerr (phase-only; kept for fidelity, cheap)
        apply_diag(S, PV, wl + 44, true, tid);
    }

    // <n_m> readout
    float a0 = 0.f, a1 = 0.f, a2 = 0.f, a3 = 0.f;
    for (int o = tid; o < 10000; o += 256) {
        int i = o/1000, j = (o/100)%10, kk = (o/10)%10, l = o%10;
        float2 s = S[o];
        float pr = s.x*s.x + s.y*s.y;
        a0 += pr * (float)i;
        a1 += pr * (float)j;
        a2 += pr * (float)kk;
        a3 += pr * (float)l;
    }
#pragma unroll
    for (int off = 16; off > 0; off >>= 1) {
        a0 += __shfl_down_sync(0xffffffffu, a0, off);
        a1 += __shfl_down_sync(0xffffffffu, a1, off);
        a2 += __shfl_down_sync(0xffffffffu, a2, off);
        a3 += __shfl_down_sync(0xffffffffu, a3, off);
    }
    int wid = tid / 32, lane = tid % 32;
    if (lane == 0) {
        red[wid*4 + 0] = a0; red[wid*4 + 1] = a1;
        red[wid*4 + 2] = a2; red[wid*4 + 3] = a3;
    }
    __syncthreads();
    if (tid < 4) {
        float s = 0.f;
        for (int ww = 0; ww < 8; ++ww) s += red[ww*4 + tid];
        out[b*4 + tid] = s;
    }
}

// ---------------------------------------------------------------------------
// Launch
// ---------------------------------------------------------------------------
#define CIRCUIT_SMEM (11040 * (int)sizeof(float2))   // 88320 bytes

extern "C" void kernel_launch(void* const* d_in, const int* in_sizes, int n_in,
                              void* d_out, int out_size)
{
    const float* inputs  = (const float*)d_in[0];
    const float* weights = (const float*)d_in[1];
    float* out = (float*)d_out;

    cudaFuncSetAttribute(circuit, cudaFuncAttributeMaxDynamicSharedMemorySize, CIRCUIT_SMEM);

    build_gates<<<NJOBS, 128>>>(inputs, weights);
    init_psi<<<4, 256>>>();
    circuit<<<BATCH, 256, CIRCUIT_SMEM>>>(weights, out);
}

// round 2
// speedup vs baseline: 1.4575x; 1.4575x over previous
#include <cuda_runtime.h>
#include <math.h>

// Problem constants
#define CUTN    10
#define DMODES  4
#define BATCH   256
#define NLAYERS 4
#define PW      48
#define NBS     48
#define NSEC    19

// Padded state strides (float2 units). All ODD so that cross-lane access
// patterns at any single stride have gcd(2*s, 32) = 2 -> conflict-light LDS.
#define S0P 1111
#define S1P 111
#define S2P 11
#define S3P 1
#define SSZ (9*S0P + 9*S1P + 9*S2P + 9*S3P + 1)   // 11107 float2

// ---------------------------------------------------------------------------
__device__ __forceinline__ float2 cmul(float2 a, float2 b) {
    return make_float2(a.x*b.x - a.y*b.y, a.x*b.y + a.y*b.x);
}
__device__ __forceinline__ float2 cfma(float2 a, float2 b, float2 acc) {
    acc.x += a.x*b.x - a.y*b.y;
    acc.y += a.x*b.y + a.y*b.x;
    return acc;
}

// ---------------------------------------------------------------------------
// Device scratch
// ---------------------------------------------------------------------------
__device__ float2 g_bs[NBS][100][10];      // banded BS gates [gate][xi*10+xj][t]
__device__ float2 g_sq[16][100];
__device__ float2 g_dp[16][100];
__device__ float2 g_S0[100];
__device__ float2 g_Dm[BATCH*DMODES][100];
__device__ float2 g_psi[BATCH][DMODES][CUTN];

// Per-pair strides: pair index p over (0,1),(0,2),(0,3),(1,2),(1,3),(2,3)
__constant__ int cSI[6] = {S0P,S0P,S0P,S1P,S1P,S2P};
__constant__ int cSJ[6] = {S1P,S2P,S3P,S2P,S3P,S3P};
__constant__ int cSA[6] = {S2P,S1P,S1P,S0P,S0P,S0P};  // larger rest stride
__constant__ int cSB[6] = {S3P,S3P,S2P,S3P,S2P,S1P};  // smaller rest stride
// Per-mode strides for single-mode gates
__constant__ int cMS[4] = {S0P,S1P,S2P,S3P};
__constant__ int cR0[4] = {S1P,S0P,S0P,S0P};
__constant__ int cR1[4] = {S2P,S2P,S1P,S1P};
__constant__ int cR2[4] = {S3P,S3P,S3P,S2P};

// ---------------------------------------------------------------------------
// Kernel 1: build gate matrices via expm (scaling+squaring, Taylor). Jobs:
//   0: S0;  1..1024: input displacements;  1025..1040: squeeze;
//   1041..1056: layer displacement;  1057..: BS sector expms -> banded g_bs
// ---------------------------------------------------------------------------
#define NJOBS (1 + 1024 + 16 + 16 + NBS*NSEC)

__global__ void build_gates(const float* __restrict__ inputs,
                            const float* __restrict__ w)
{
    __shared__ float2 A[100], E[100], P[100], T[100];
    const int job = blockIdx.x;
    const int tid = threadIdx.x;

    int d = CUTN;
    int lo = 0, N = 0, g = 0;
    const bool isBS = (job >= 1057);
    if (isBS) {
        int idx = job - 1057;
        g = idx / NSEC;  N = idx % NSEC;
        lo = max(0, N - (CUTN-1));
        int hi = min(CUTN-1, N);
        d = hi - lo + 1;
    }

    if (tid < d*d) {
        int i = tid / d, j = tid % d;
        float2 v = make_float2(0.f, 0.f);
        if (job == 0) {
            if (i == j-2)      v = make_float2(0.f, -0.25f * sqrtf((float)(j*(j-1))));
            else if (i == j+2) v = make_float2(0.f, -0.25f * sqrtf((float)((j+1)*(j+2))));
        } else if (job <= 1024) {
            float xv = inputs[job-1];
            if (i == j+1)      v = make_float2( xv * sqrtf((float)(j+1)), 0.f);
            else if (i == j-1) v = make_float2(-xv * sqrtf((float)j),     0.f);
        } else if (job <= 1040) {
            int q = job - 1025; int l = q/4, m = q%4;
            float r = w[l*PW + 16 + m];
            if (i == j-2)      v = make_float2( 0.5f*r*sqrtf((float)(j*(j-1))),     0.f);
            else if (i == j+2) v = make_float2(-0.5f*r*sqrtf((float)((j+1)*(j+2))), 0.f);
        } else if (job <= 1056) {
            int q = job - 1041; int l = q/4, m = q%4;
            float rd = w[l*PW + 36 + m];
            float ph = w[l*PW + 40 + m];
            float ax = rd*cosf(ph), ay = rd*sinf(ph);
            if (i == j+1)      { float s = sqrtf((float)(j+1)); v = make_float2( ax*s,  ay*s); }
            else if (i == j-1) { float s = sqrtf((float)j);     v = make_float2(-ax*s,  ay*s); }
        } else {
            int l = g / 12; int h = (g % 12) / 6; int p = g % 6;
            float th = w[l*PW + (h ? 20 : 0) + p];
            float ph = w[l*PW + (h ? 26 : 6) + p];
            float cp = cosf(ph), sp = sinf(ph);
            int yi = lo + j; int yj = N - yi;
            if (i == j+1)      { float s = th * sqrtf((float)((yi+1)*yj)); v = make_float2( cp*s, sp*s); }
            else if (i == j-1) { float s = th * sqrtf((float)(yi*(yj+1))); v = make_float2(-cp*s, sp*s); }
        }
        A[tid] = v;
    }
    __syncthreads();

    const float SC = 1.0f/256.0f;
    if (tid < d*d) {
        int i = tid/d;
        float2 m0 = make_float2(A[tid].x*SC, A[tid].y*SC);
        P[tid] = m0;
        E[tid] = make_float2(((tid % d) == i ? 1.f : 0.f) + m0.x, m0.y);
    }
    __syncthreads();
    for (int k = 2; k <= 8; ++k) {
        float2 t = make_float2(0.f, 0.f);
        if (tid < d*d) {
            int i = tid/d, j = tid%d;
            for (int u = 0; u < d; ++u)
                t = cfma(P[i*d+u], A[u*d+j], t);
            float f = SC / (float)k;
            t.x *= f; t.y *= f;
        }
        __syncthreads();
        if (tid < d*d) {
            T[tid] = t;
            E[tid].x += t.x; E[tid].y += t.y;
            P[tid] = t;
        }
        __syncthreads();
    }
    for (int s = 0; s < 8; ++s) {
        float2 t = make_float2(0.f, 0.f);
        if (tid < d*d) {
            int i = tid/d, j = tid%d;
            for (int u = 0; u < d; ++u)
                t = cfma(E[i*d+u], E[u*d+j], t);
        }
        __syncthreads();
        if (tid < d*d) E[tid] = t;
        __syncthreads();
    }

    if (job == 0) {
        if (tid < 100) g_S0[tid] = E[tid];
    } else if (job <= 1024) {
        if (tid < 100) g_Dm[job-1][tid] = E[tid];
    } else if (job <= 1040) {
        if (tid < 100) g_sq[job-1025][tid] = E[tid];
    } else if (job <= 1056) {
        if (tid < 100) g_dp[job-1041][tid] = E[tid];
    } else {
        if (tid < d*10) {
            int x = tid/10, t = tid%10;
            int xi = lo + x, xj = N - xi;
            float2 v = (t < d) ? E[x*d + t] : make_float2(0.f, 0.f);
            g_bs[g][xi*10 + xj][t] = v;
        }
    }
}

// ---------------------------------------------------------------------------
// Kernel 2: g_psi[b][m] = Dm[b*4+m] @ S0[:,0]
// ---------------------------------------------------------------------------
__global__ void init_psi()
{
    int t = blockIdx.x * blockDim.x + threadIdx.x;
    if (t >= BATCH*DMODES) return;
    float2 p0[CUTN];
#pragma unroll
    for (int y = 0; y < CUTN; ++y) p0[y] = g_S0[y*CUTN + 0];
    const float2* Dm = g_Dm[t];
#pragma unroll
    for (int i = 0; i < CUTN; ++i) {
        float2 acc = make_float2(0.f, 0.f);
#pragma unroll
        for (int y = 0; y < CUTN; ++y) acc = cfma(Dm[i*CUTN + y], p0[y], acc);
        g_psi[t/DMODES][t%DMODES][i] = acc;
    }
}

// ---------------------------------------------------------------------------
// Circuit kernel: one CTA per batch element, padded state in SMEM.
// BS gate = 1900 independent (sector, fiber) items, each owned by one thread:
// load d inputs -> regs, d*d cMAC, write d outputs in place. No intra-gate sync.
// ---------------------------------------------------------------------------
__device__ __forceinline__ int paddr(int o) {
    int i = o / 1000, j = (o/100) % 10, k = (o/10) % 10;
    return o + i*111 + j*11 + k;     // == i*1111 + j*111 + k*11 + l
}

template<int D>
__device__ __forceinline__ void bs_item(float2* S, const float2* Ub,
                                        int caddr, int ds, int ur0)
{
    float2 in[D];
#pragma unroll
    for (int t = 0; t < D; ++t) in[t] = S[caddr + t*ds];
#pragma unroll
    for (int x = 0; x < D; ++x) {
        float2 acc = make_float2(0.f, 0.f);
        const float2* Ur = Ub + ur0 + x*90;   // row xi=lo+x -> U[(9*(lo+x)+N)*10]
#pragma unroll
        for (int t = 0; t < D; ++t) acc = cfma(Ur[t], in[t], acc);
        S[caddr + x*ds] = acc;
    }
}

__device__ __forceinline__ void apply_bs(float2* S, float2* Ub, int g, int p, int tid)
{
    const float2* src = &g_bs[g][0][0];
    for (int q = tid; q < 1000; q += 256) Ub[q] = src[q];
    __syncthreads();
    const int sj = cSJ[p], sa = cSA[p], sb = cSB[p];
    const int ds = cSI[p] - cSJ[p];

    for (int it = tid; it < 1900; it += 256) {
        int N  = it / 100;
        int f  = it - N*100;
        int fa = f / 10, fb = f - fa*10;
        int base = fa*sa + fb*sb;
        int lo = (N > 9) ? N - 9 : 0;
        int hi = (N < 9) ? N : 9;
        int d  = hi - lo + 1;
        int caddr = base + N*sj + lo*ds;
        int ur0   = (9*lo + N)*10;
        switch (d) {
            case  1: bs_item< 1>(S, Ub, caddr, ds, ur0); break;
            case  2: bs_item< 2>(S, Ub, caddr, ds, ur0); break;
            case  3: bs_item< 3>(S, Ub, caddr, ds, ur0); break;
            case  4: bs_item< 4>(S, Ub, caddr, ds, ur0); break;
            case  5: bs_item< 5>(S, Ub, caddr, ds, ur0); break;
            case  6: bs_item< 6>(S, Ub, caddr, ds, ur0); break;
            case  7: bs_item< 7>(S, Ub, caddr, ds, ur0); break;
            case  8: bs_item< 8>(S, Ub, caddr, ds, ur0); break;
            case  9: bs_item< 9>(S, Ub, caddr, ds, ur0); break;
            default: bs_item<10>(S, Ub, caddr, ds, ur0); break;
        }
    }
    __syncthreads();
}

__device__ __forceinline__ void apply_single(float2* S, float2* Ub,
                                             const float2* Ug, int m, int tid)
{
    for (int q = tid; q < 100; q += 256) Ub[q] = Ug[q];
    __syncthreads();
    const int sm = cMS[m], r0 = cR0[m], r1 = cR1[m], r2 = cR2[m];
    for (int it = tid; it < 1000; it += 256) {
        int f0 = it / 100; int r = it - f0*100;
        int f1 = r / 10;   int f2 = r - f1*10;
        int base = f0*r0 + f1*r1 + f2*r2;
        float2 in[10];
#pragma unroll
        for (int y = 0; y < 10; ++y) in[y] = S[base + y*sm];
#pragma unroll
        for (int x = 0; x < 10; ++x) {
            float2 acc = make_float2(0.f, 0.f);
#pragma unroll
            for (int y = 0; y < 10; ++y) acc = cfma(Ub[x*10 + y], in[y], acc);
            S[base + x*sm] = acc;
        }
    }
    __syncthreads();
}

__device__ __forceinline__ void apply_diag(float2* S, float2* PV,
                                           const float* v, bool kerr, int tid)
{
    if (tid < 40) {
        int m = tid / 10, n = tid % 10;
        float ang = v[m] * (kerr ? (float)(n*n) : (float)n);
        float sn, cs; sincosf(ang, &sn, &cs);
        PV[tid] = make_float2(cs, sn);
    }
    __syncthreads();
    for (int o = tid; o < 10000; o += 256) {
        int i = o/1000, j = (o/100)%10, kk = (o/10)%10, l = o%10;
        float2 ph = cmul(cmul(PV[i], PV[10+j]), cmul(PV[20+kk], PV[30+l]));
        int a = o + i*111 + j*11 + kk;
        S[a] = cmul(S[a], ph);
    }
    __syncthreads();
}

__global__ void __launch_bounds__(256, 2)
circuit(const float* __restrict__ w, float* __restrict__ out)
{
    extern __shared__ float2 sh[];
    float2* S  = sh;            // SSZ = 11107
    float2* Ub = sh + SSZ;      // 1000
    float2* PV = sh + SSZ + 1000; // 40
    __shared__ float red[8*4];

    const int b = blockIdx.x, tid = threadIdx.x;

    // initial product state
    if (tid < 40) PV[tid] = g_psi[b][tid/10][tid%10];
    __syncthreads();
    for (int o = tid; o < 10000; o += 256) {
        int i = o/1000, j = (o/100)%10, kk = (o/10)%10, l = o%10;
        S[o + i*111 + j*11 + kk] = cmul(cmul(PV[i], PV[10+j]), cmul(PV[20+kk], PV[30+l]));
    }
    __syncthreads();

    for (int lay = 0; lay < NLAYERS; ++lay) {
        const float* wl = w + lay*PW;
        for (int p = 0; p < 6; ++p) apply_bs(S, Ub, lay*12 + p, p, tid);
        apply_diag(S, PV, wl + 12, false, tid);
        for (int m = 0; m < 4; ++m) apply_single(S, Ub, g_sq[lay*4 + m], m, tid);
        for (int p = 0; p < 6; ++p) apply_bs(S, Ub, lay*12 + 6 + p, p, tid);
        apply_diag(S, PV, wl + 32, false, tid);
        for (int m = 0; m < 4; ++m) apply_single(S, Ub, g_dp[lay*4 + m], m, tid);
        apply_diag(S, PV, wl + 44, true, tid);
    }

    // <n_m> readout
    float a0 = 0.f, a1 = 0.f, a2 = 0.f, a3 = 0.f;
    for (int o = tid; o < 10000; o += 256) {
        int i = o/1000, j = (o/100)%10, kk = (o/10)%10, l = o%10;
        float2 s = S[o + i*111 + j*11 + kk];
        float pr = s.x*s.x + s.y*s.y;
        a0 += pr * (float)i;
        a1 += pr * (float)j;
        a2 += pr * (float)kk;
        a3 += pr * (float)l;
    }
#pragma unroll
    for (int off = 16; off > 0; off >>= 1) {
        a0 += __shfl_down_sync(0xffffffffu, a0, off);
        a1 += __shfl_down_sync(0xffffffffu, a1, off);
        a2 += __shfl_down_sync(0xffffffffu, a2, off);
        a3 += __shfl_down_sync(0xffffffffu, a3, off);
    }
    int wid = tid / 32, lane = tid % 32;
    if (lane == 0) {
        red[wid*4 + 0] = a0; red[wid*4 + 1] = a1;
        red[wid*4 + 2] = a2; red[wid*4 + 3] = a3;
    }
    __syncthreads();
    if (tid < 4) {
        float s = 0.f;
        for (int ww = 0; ww < 8; ++ww) s += red[ww*4 + tid];
        out[b*4 + tid] = s;
    }
}

// ---------------------------------------------------------------------------
#define CIRCUIT_SMEM ((SSZ + 1000 + 40) * (int)sizeof(float2))   // 97176 B

extern "C" void kernel_launch(void* const* d_in, const int* in_sizes, int n_in,
                              void* d_out, int out_size)
{
    const float* inputs  = (const float*)d_in[0];
    const float* weights = (const float*)d_in[1];
    float* out = (float*)d_out;

    cudaFuncSetAttribute(circuit, cudaFuncAttributeMaxDynamicSharedMemorySize, CIRCUIT_SMEM);

    build_gates<<<NJOBS, 128>>>(inputs, weights);
    init_psi<<<4, 256>>>();
    circuit<<<BATCH, 256, CIRCUIT_SMEM>>>(weights, out);
}

// round 4
// speedup vs baseline: 2.0518x; 1.4078x over previous
#include <cuda_runtime.h>
#include <math.h>

// Problem constants
#define CUTN    10
#define DMODES  4
#define BATCH   256
#define NLAYERS 4
#define PW      48
#define NBS     48
#define NSEC    19

// Padded state strides (float2 units), all odd -> conflict-light LDS
#define S0P 1111
#define S1P 111
#define S2P 11
#define S3P 1
#define SSZ (9*S0P + 9*S1P + 9*S2P + 9*S3P + 1)   // 11107 float2

typedef unsigned long long u64;

// ---------------------------------------------------------------------------
__device__ __forceinline__ float2 cmul(float2 a, float2 b) {
    return make_float2(a.x*b.x - a.y*b.y, a.x*b.y + a.y*b.x);
}
__device__ __forceinline__ float2 cfma(float2 a, float2 b, float2 acc) {
    acc.x += a.x*b.x - a.y*b.y;
    acc.y += a.x*b.y + a.y*b.x;
    return acc;
}

#define FMA2(acc, a, b) \
    asm("fma.rn.f32x2 %0, %1, %2, %0;" : "+l"(acc) : "l"(a), "l"(b))

// ---------------------------------------------------------------------------
// Device scratch
// ---------------------------------------------------------------------------
__device__ float2 g_bs[NBS][100][10];      // banded BS gates [gate][xi*10+xj][t]
__device__ float2 g_sq[16][100];
__device__ float2 g_dp[16][100];
__device__ float2 g_S0[100];
__device__ float2 g_Dm[BATCH*DMODES][100];
__device__ float2 g_psi[BATCH][DMODES][CUTN];

// Pair strides: p over (0,1),(0,2),(0,3),(1,2),(1,3),(2,3)
__constant__ int cSI[6] = {S0P,S0P,S0P,S1P,S1P,S2P};
__constant__ int cSJ[6] = {S1P,S2P,S3P,S2P,S3P,S3P};
__constant__ int cSA[6] = {S2P,S1P,S1P,S0P,S0P,S0P};
__constant__ int cSB[6] = {S3P,S3P,S2P,S3P,S2P,S1P};
__constant__ int cMS[4] = {S0P,S1P,S2P,S3P};
__constant__ int cR0[4] = {S1P,S0P,S0P,S0P};
__constant__ int cR1[4] = {S2P,S2P,S1P,S1P};
__constant__ int cR2[4] = {S3P,S3P,S3P,S2P};

// Weight layout per layer: th1:0 ph1:6 vp1:12 rsq:16 th2:20 ph2:26 vp2:32 rd:36 phd:40 kap:44

// ---------------------------------------------------------------------------
// Kernel 1: build all gate matrices (expm via scaling+squaring), with the
// phase diagonals FOLDED IN as column scalings:
//   squeeze[l][m]      <- U_sq  @ diag(e^{i vp1 n})
//   displacement[l][m] <- U_dp  @ diag(e^{i vp2 n})
//   BS interferometer-1 of layer l>=1 <- U_bs @ Kerr(layer l-1) columns
//   final layer's Kerr: dropped (phase-only, invisible to |psi|^2)
// ---------------------------------------------------------------------------
#define NJOBS (1 + 1024 + 16 + 16 + NBS*NSEC)

__global__ void build_gates(const float* __restrict__ inputs,
                            const float* __restrict__ w)
{
    __shared__ float2 A[100], E[100], P[100];
    const int job = blockIdx.x;
    const int tid = threadIdx.x;

    int d = CUTN;
    int lo = 0, N = 0, g = 0;
    const bool isBS = (job >= 1057);
    if (isBS) {
        int idx = job - 1057;
        g = idx / NSEC;  N = idx % NSEC;
        lo = max(0, N - (CUTN-1));
        int hi = min(CUTN-1, N);
        d = hi - lo + 1;
    }

    if (tid < d*d) {
        int i = tid / d, j = tid % d;
        float2 v = make_float2(0.f, 0.f);
        if (job == 0) {
            if (i == j-2)      v = make_float2(0.f, -0.25f * sqrtf((float)(j*(j-1))));
            else if (i == j+2) v = make_float2(0.f, -0.25f * sqrtf((float)((j+1)*(j+2))));
        } else if (job <= 1024) {
            float xv = inputs[job-1];
            if (i == j+1)      v = make_float2( xv * sqrtf((float)(j+1)), 0.f);
            else if (i == j-1) v = make_float2(-xv * sqrtf((float)j),     0.f);
        } else if (job <= 1040) {
            int q = job - 1025; int l = q/4, m = q%4;
            float r = w[l*PW + 16 + m];
            if (i == j-2)      v = make_float2( 0.5f*r*sqrtf((float)(j*(j-1))),     0.f);
            else if (i == j+2) v = make_float2(-0.5f*r*sqrtf((float)((j+1)*(j+2))), 0.f);
        } else if (job <= 1056) {
            int q = job - 1041; int l = q/4, m = q%4;
            float rd = w[l*PW + 36 + m];
            float ph = w[l*PW + 40 + m];
            float ax = rd*cosf(ph), ay = rd*sinf(ph);
            if (i == j+1)      { float s = sqrtf((float)(j+1)); v = make_float2( ax*s,  ay*s); }
            else if (i == j-1) { float s = sqrtf((float)j);     v = make_float2(-ax*s,  ay*s); }
        } else {
            int l = g / 12; int h = (g % 12) / 6; int p = g % 6;
            float th = w[l*PW + (h ? 20 : 0) + p];
            float ph = w[l*PW + (h ? 26 : 6) + p];
            float cp = cosf(ph), sp = sinf(ph);
            int yi = lo + j; int yj = N - yi;
            if (i == j+1)      { float s = th * sqrtf((float)((yi+1)*yj)); v = make_float2( cp*s, sp*s); }
            else if (i == j-1) { float s = th * sqrtf((float)(yi*(yj+1))); v = make_float2(-cp*s, sp*s); }
        }
        A[tid] = v;
    }
    __syncthreads();

    const float SC = 1.0f/256.0f;
    if (tid < d*d) {
        int i = tid/d;
        float2 m0 = make_float2(A[tid].x*SC, A[tid].y*SC);
        P[tid] = m0;
        E[tid] = make_float2(((tid % d) == i ? 1.f : 0.f) + m0.x, m0.y);
    }
    __syncthreads();
    for (int k = 2; k <= 8; ++k) {
        float2 t = make_float2(0.f, 0.f);
        if (tid < d*d) {
            int i = tid/d, j = tid%d;
            for (int u = 0; u < d; ++u)
                t = cfma(P[i*d+u], A[u*d+j], t);
            float f = SC / (float)k;
            t.x *= f; t.y *= f;
        }
        __syncthreads();
        if (tid < d*d) {
            E[tid].x += t.x; E[tid].y += t.y;
            P[tid] = t;
        }
        __syncthreads();
    }
    for (int s = 0; s < 8; ++s) {
        float2 t = make_float2(0.f, 0.f);
        if (tid < d*d) {
            int i = tid/d, j = tid%d;
            for (int u = 0; u < d; ++u)
                t = cfma(E[i*d+u], E[u*d+j], t);
        }
        __syncthreads();
        if (tid < d*d) E[tid] = t;
        __syncthreads();
    }

    if (job == 0) {
        if (tid < 100) g_S0[tid] = E[tid];
    } else if (job <= 1024) {
        if (tid < 100) g_Dm[job-1][tid] = E[tid];
    } else if (job <= 1040) {
        // squeeze with vp1 fold (column phase e^{i vp1 * j})
        int q = job - 1025; int l = q/4, m = q%4;
        float vp = w[l*PW + 12 + m];
        if (tid < 100) {
            int j = tid % 10;
            float sn, cs; sincosf(vp * (float)j, &sn, &cs);
            g_sq[q][tid] = cmul(E[tid], make_float2(cs, sn));
        }
    } else if (job <= 1056) {
        // displacement with vp2 fold
        int q = job - 1041; int l = q/4, m = q%4;
        float vp = w[l*PW + 32 + m];
        if (tid < 100) {
            int j = tid % 10;
            float sn, cs; sincosf(vp * (float)j, &sn, &cs);
            g_dp[q][tid] = cmul(E[tid], make_float2(cs, sn));
        }
    } else {
        // banded BS writeback, with previous layer's Kerr folded into the
        // first interferometer's gates (columns scaled by Kerr phases)
        if (tid < d*10) {
            int x = tid/10, t = tid%10;
            int xi = lo + x, xj = N - xi;
            float2 v = (t < d) ? E[x*d + t] : make_float2(0.f, 0.f);
            int l = g / 12, h = (g % 12) / 6, p = g % 6;
            if (t < d && h == 0 && l > 0) {
                int yi = lo + t, yj = N - yi;
                const float* kap = w + (l-1)*PW + 44;
                float ang = 0.f;
                if (p == 0)      ang = kap[0]*(float)(yi*yi) + kap[1]*(float)(yj*yj);
                else if (p == 1) ang = kap[2]*(float)(yj*yj);
                else if (p == 2) ang = kap[3]*(float)(yj*yj);
                if (ang != 0.f) {
                    float sn, cs; sincosf(ang, &sn, &cs);
                    v = cmul(v, make_float2(cs, sn));
                }
            }
            g_bs[g][xi*10 + xj][t] = v;
        }
    }
}

// ---------------------------------------------------------------------------
// Kernel 2: g_psi[b][m] = Dm[b*4+m] @ S0[:,0]
// ---------------------------------------------------------------------------
__global__ void init_psi()
{
    int t = blockIdx.x * blockDim.x + threadIdx.x;
    if (t >= BATCH*DMODES) return;
    float2 p0[CUTN];
#pragma unroll
    for (int y = 0; y < CUTN; ++y) p0[y] = g_S0[y*CUTN + 0];
    const float2* Dm = g_Dm[t];
#pragma unroll
    for (int i = 0; i < CUTN; ++i) {
        float2 acc = make_float2(0.f, 0.f);
#pragma unroll
        for (int y = 0; y < CUTN; ++y) acc = cfma(Dm[i*CUTN + y], p0[y], acc);
        g_psi[t/DMODES][t%DMODES][i] = acc;
    }
}

// ---------------------------------------------------------------------------
// Circuit kernel. Complex MAC via packed f32x2 FMA:
//   out += u * in :
//     FMA2 with (u.x,u.y)*(in.x,in.x)  -> (u.x in.x, u.y in.x)
//     FMA2 with (u.y,u.x)*(-in.y,in.y) -> (-u.y in.y, u.x in.y)
// (u.y,u.x) is pre-staged in a second smem buffer so each cMAC is
// exactly 2 LDS.64 + 2 FMA2.
// ---------------------------------------------------------------------------
template<int D>
__device__ __forceinline__ void bs_item(u64* Su,
        const u64* __restrict__ Ub, const u64* __restrict__ Ubs,
        int caddr, int ds, int ur0)
{
    u64 inxx[D], inyy[D];
#pragma unroll
    for (int t = 0; t < D; ++t) {
        float2 v = ((const float2*)Su)[caddr + t*ds];
        float nvy = -v.y;
        asm("mov.b64 %0, {%1, %1};" : "=l"(inxx[t]) : "f"(v.x));
        asm("mov.b64 %0, {%1, %2};" : "=l"(inyy[t]) : "f"(nvy), "f"(v.y));
    }
#pragma unroll
    for (int x = 0; x < D; ++x) {
        u64 acc = 0ULL;
        const u64* Ur  = Ub  + ur0 + x*90;
        const u64* Urs = Ubs + ur0 + x*90;
#pragma unroll
        for (int t = 0; t < D; ++t) {
            FMA2(acc, Ur[t],  inxx[t]);
            FMA2(acc, Urs[t], inyy[t]);
        }
        Su[caddr + x*ds] = acc;
    }
}

__device__ __forceinline__ void apply_bs(u64* Su, float2* Ub, float2* Ubs,
                                         int g, int p, int tid, int nt)
{
    const float2* src = &g_bs[g][0][0];
    for (int q = tid; q < 1000; q += nt) {
        float2 u = src[q];
        Ub[q]  = u;
        Ubs[q] = make_float2(u.y, u.x);
    }
    __syncthreads();
    const int sj = cSJ[p], sa = cSA[p], sb = cSB[p];
    const int ds = cSI[p] - cSJ[p];
    const u64* Ub64  = (const u64*)Ub;
    const u64* Ubs64 = (const u64*)Ubs;

    for (int it = tid; it < 1900; it += nt) {
        int N  = it / 100;
        int f  = it - N*100;
        int fa = f / 10, fb = f - fa*10;
        int base = fa*sa + fb*sb;
        int lo = (N > 9) ? N - 9 : 0;
        int hi = (N < 9) ? N : 9;
        int d  = hi - lo + 1;
        int caddr = base + N*sj + lo*ds;
        int ur0   = (9*lo + N)*10;
        switch (d) {
            case  1: bs_item< 1>(Su, Ub64, Ubs64, caddr, ds, ur0); break;
            case  2: bs_item< 2>(Su, Ub64, Ubs64, caddr, ds, ur0); break;
            case  3: bs_item< 3>(Su, Ub64, Ubs64, caddr, ds, ur0); break;
            case  4: bs_item< 4>(Su, Ub64, Ubs64, caddr, ds, ur0); break;
            case  5: bs_item< 5>(Su, Ub64, Ubs64, caddr, ds, ur0); break;
            case  6: bs_item< 6>(Su, Ub64, Ubs64, caddr, ds, ur0); break;
            case  7: bs_item< 7>(Su, Ub64, Ubs64, caddr, ds, ur0); break;
            case  8: bs_item< 8>(Su, Ub64, Ubs64, caddr, ds, ur0); break;
            case  9: bs_item< 9>(Su, Ub64, Ubs64, caddr, ds, ur0); break;
            default: bs_item<10>(Su, Ub64, Ubs64, caddr, ds, ur0); break;
        }
    }
    __syncthreads();
}

__device__ __forceinline__ void apply_single(u64* Su, float2* Ub, float2* Ubs,
                                             const float2* Ug, int m, int tid, int nt)
{
    for (int q = tid; q < 100; q += nt) {
        float2 u = Ug[q];
        Ub[q]  = u;
        Ubs[q] = make_float2(u.y, u.x);
    }
    __syncthreads();
    const int sm = cMS[m], r0 = cR0[m], r1 = cR1[m], r2 = cR2[m];
    const u64* Ub64  = (const u64*)Ub;
    const u64* Ubs64 = (const u64*)Ubs;

    for (int it = tid; it < 1000; it += nt) {
        int f0 = it / 100; int r = it - f0*100;
        int f1 = r / 10;   int f2 = r - f1*10;
        int base = f0*r0 + f1*r1 + f2*r2;
        u64 inxx[10], inyy[10];
#pragma unroll
        for (int y = 0; y < 10; ++y) {
            float2 v = ((const float2*)Su)[base + y*sm];
            float nvy = -v.y;
            asm("mov.b64 %0, {%1, %1};" : "=l"(inxx[y]) : "f"(v.x));
            asm("mov.b64 %0, {%1, %2};" : "=l"(inyy[y]) : "f"(nvy), "f"(v.y));
        }
#pragma unroll
        for (int x = 0; x < 10; ++x) {
            u64 acc = 0ULL;
#pragma unroll
            for (int y = 0; y < 10; ++y) {
                FMA2(acc, Ub64[x*10 + y],  inxx[y]);
                FMA2(acc, Ubs64[x*10 + y], inyy[y]);
            }
            Su[base + x*sm] = acc;
        }
    }
    __syncthreads();
}

__global__ void __launch_bounds__(256, 2)
circuit(const float* __restrict__ w, float* __restrict__ out)
{
    extern __shared__ float2 sh[];
    float2* S   = sh;                   // 11107
    float2* Ub  = sh + SSZ;             // 1000
    float2* Ubs = sh + SSZ + 1000;      // 1000
    float2* PV  = sh + SSZ + 2000;      // 40
    __shared__ float red[8*4];

    const int b = blockIdx.x, tid = threadIdx.x;
    const int nt = blockDim.x;
    u64* Su = (u64*)S;

    // initial product state
    if (tid < 40) PV[tid] = g_psi[b][tid/10][tid%10];
    __syncthreads();
    for (int o = tid; o < 10000; o += nt) {
        int i = o/1000, j = (o/100)%10, kk = (o/10)%10, l = o%10;
        S[o + i*111 + j*11 + kk] = cmul(cmul(PV[i], PV[10+j]), cmul(PV[20+kk], PV[30+l]));
    }
    __syncthreads();

    for (int lay = 0; lay < NLAYERS; ++lay) {
        for (int p = 0; p < 6; ++p) apply_bs(Su, Ub, Ubs, lay*12 + p, p, tid, nt);
        for (int m = 0; m < 4; ++m) apply_single(Su, Ub, Ubs, g_sq[lay*4 + m], m, tid, nt);
        for (int p = 0; p < 6; ++p) apply_bs(Su, Ub, Ubs, lay*12 + 6 + p, p, tid, nt);
        for (int m = 0; m < 4; ++m) apply_single(Su, Ub, Ubs, g_dp[lay*4 + m], m, tid, nt);
    }

    // <n_m> readout
    float a0 = 0.f, a1 = 0.f, a2 = 0.f, a3 = 0.f;
    for (int o = tid; o < 10000; o += nt) {
        int i = o/1000, j = (o/100)%10, kk = (o/10)%10, l = o%10;
        float2 s = S[o + i*111 + j*11 + kk];
        float pr = s.x*s.x + s.y*s.y;
        a0 += pr * (float)i;
        a1 += pr * (float)j;
        a2 += pr * (float)kk;
        a3 += pr * (float)l;
    }
#pragma unroll
    for (int off = 16; off > 0; off >>= 1) {
        a0 += __shfl_down_sync(0xffffffffu, a0, off);
        a1 += __shfl_down_sync(0xffffffffu, a1, off);
        a2 += __shfl_down_sync(0xffffffffu, a2, off);
        a3 += __shfl_down_sync(0xffffffffu, a3, off);
    }
    int wid = tid / 32, lane = tid % 32;
    if (lane == 0) {
        red[wid*4 + 0] = a0; red[wid*4 + 1] = a1;
        red[wid*4 + 2] = a2; red[wid*4 + 3] = a3;
    }
    __syncthreads();
    if (tid < 4) {
        float s = 0.f;
        for (int ww = 0; ww < 8; ++ww) s += red[ww*4 + tid];
        out[b*4 + tid] = s;
    }
}

// ---------------------------------------------------------------------------
#define CIRCUIT_SMEM ((SSZ + 2000 + 40) * (int)sizeof(float2))   // 105176 B

extern "C" void kernel_launch(void* const* d_in, const int* in_sizes, int n_in,
                              void* d_out, int out_size)
{
    const float* inputs  = (const float*)d_in[0];
    const float* weights = (const float*)d_in[1];
    float* out = (float*)d_out;

    cudaFuncSetAttribute(circuit, cudaFuncAttributeMaxDynamicSharedMemorySize, CIRCUIT_SMEM);

    build_gates<<<NJOBS, 128>>>(inputs, weights);
    init_psi<<<4, 256>>>();
    circuit<<<BATCH, 256, CIRCUIT_SMEM>>>(weights, out);
}

// round 6
// speedup vs baseline: 2.0614x; 1.0047x over previous
#include <cuda_runtime.h>
#include <math.h>

// Problem constants
#define CUTN    10
#define DMODES  4
#define BATCH   256
#define NLAYERS 4
#define PW      48
#define NBS     48
#define NSEC    19

#define NTHR    384

// Padded state strides (float2 units), all odd -> conflict-light LDS
#define S0P 1111
#define S1P 111
#define S2P 11
#define S3P 1
#define SSZ (9*S0P + 9*S1P + 9*S2P + 9*S3P + 1)   // 11107 float2

typedef unsigned long long u64;

// ---------------------------------------------------------------------------
__device__ __forceinline__ float2 cmul(float2 a, float2 b) {
    return make_float2(a.x*b.x - a.y*b.y, a.x*b.y + a.y*b.x);
}
__device__ __forceinline__ float2 cfma(float2 a, float2 b, float2 acc) {
    acc.x += a.x*b.x - a.y*b.y;
    acc.y += a.x*b.y + a.y*b.x;
    return acc;
}

#define FMA2(acc, a, b) \
    asm("fma.rn.f32x2 %0, %1, %2, %0;" : "+l"(acc) : "l"(a), "l"(b))
#define ADD2(out, a, b) \
    asm("add.rn.f32x2 %0, %1, %2;" : "=l"(out) : "l"(a), "l"(b))

// ---------------------------------------------------------------------------
// Device scratch
// ---------------------------------------------------------------------------
__device__ float2 g_bs[NBS][100][10];      // banded BS gates [gate][xi*10+xj][t]
__device__ float2 g_sq[16][100];
__device__ float2 g_dp[16][100];
__device__ float2 g_S0[100];
__device__ float2 g_Dm[BATCH*DMODES][100];
__device__ float2 g_psi[BATCH][DMODES][CUTN];

// Pair strides: p over (0,1),(0,2),(0,3),(1,2),(1,3),(2,3)
__constant__ int cSI[6] = {S0P,S0P,S0P,S1P,S1P,S2P};
__constant__ int cSJ[6] = {S1P,S2P,S3P,S2P,S3P,S3P};
__constant__ int cSA[6] = {S2P,S1P,S1P,S0P,S0P,S0P};
__constant__ int cSB[6] = {S3P,S3P,S2P,S3P,S2P,S1P};
__constant__ int cMS[4] = {S0P,S1P,S2P,S3P};
__constant__ int cR0[4] = {S1P,S0P,S0P,S0P};
__constant__ int cR1[4] = {S2P,S2P,S1P,S1P};
__constant__ int cR2[4] = {S3P,S3P,S3P,S2P};

// Weight layout per layer: th1:0 ph1:6 vp1:12 rsq:16 th2:20 ph2:26 vp2:32 rd:36 phd:40 kap:44

// ---------------------------------------------------------------------------
// Kernel 1: build all gate matrices (expm via scaling+squaring), with the
// phase diagonals FOLDED IN as column scalings:
//   squeeze[l][m]      <- U_sq  @ diag(e^{i vp1 n})
//   displacement[l][m] <- U_dp  @ diag(e^{i vp2 n})
//   BS interferometer-1 of layer l>=1 <- U_bs @ Kerr(layer l-1) columns
//   final layer's Kerr: dropped (phase-only, invisible to |psi|^2)
// ---------------------------------------------------------------------------
#define NJOBS (1 + 1024 + 16 + 16 + NBS*NSEC)

__global__ void build_gates(const float* __restrict__ inputs,
                            const float* __restrict__ w)
{
    __shared__ float2 A[100], E[100], P[100];
    const int job = blockIdx.x;
    const int tid = threadIdx.x;

    int d = CUTN;
    int lo = 0, N = 0, g = 0;
    const bool isBS = (job >= 1057);
    if (isBS) {
        int idx = job - 1057;
        g = idx / NSEC;  N = idx % NSEC;
        lo = max(0, N - (CUTN-1));
        int hi = min(CUTN-1, N);
        d = hi - lo + 1;
    }

    if (tid < d*d) {
        int i = tid / d, j = tid % d;
        float2 v = make_float2(0.f, 0.f);
        if (job == 0) {
            if (i == j-2)      v = make_float2(0.f, -0.25f * sqrtf((float)(j*(j-1))));
            else if (i == j+2) v = make_float2(0.f, -0.25f * sqrtf((float)((j+1)*(j+2))));
        } else if (job <= 1024) {
            float xv = inputs[job-1];
            if (i == j+1)      v = make_float2( xv * sqrtf((float)(j+1)), 0.f);
            else if (i == j-1) v = make_float2(-xv * sqrtf((float)j),     0.f);
        } else if (job <= 1040) {
            int q = job - 1025; int l = q/4, m = q%4;
            float r = w[l*PW + 16 + m];
            if (i == j-2)      v = make_float2( 0.5f*r*sqrtf((float)(j*(j-1))),     0.f);
            else if (i == j+2) v = make_float2(-0.5f*r*sqrtf((float)((j+1)*(j+2))), 0.f);
        } else if (job <= 1056) {
            int q = job - 1041; int l = q/4, m = q%4;
            float rd = w[l*PW + 36 + m];
            float ph = w[l*PW + 40 + m];
            float ax = rd*cosf(ph), ay = rd*sinf(ph);
            if (i == j+1)      { float s = sqrtf((float)(j+1)); v = make_float2( ax*s,  ay*s); }
            else if (i == j-1) { float s = sqrtf((float)j);     v = make_float2(-ax*s,  ay*s); }
        } else {
            int l = g / 12; int h = (g % 12) / 6; int p = g % 6;
            float th = w[l*PW + (h ? 20 : 0) + p];
            float ph = w[l*PW + (h ? 26 : 6) + p];
            float cp = cosf(ph), sp = sinf(ph);
            int yi = lo + j; int yj = N - yi;
            if (i == j+1)      { float s = th * sqrtf((float)((yi+1)*yj)); v = make_float2( cp*s, sp*s); }
            else if (i == j-1) { float s = th * sqrtf((float)(yi*(yj+1))); v = make_float2(-cp*s, sp*s); }
        }
        A[tid] = v;
    }
    __syncthreads();

    const float SC = 1.0f/256.0f;
    if (tid < d*d) {
        int i = tid/d;
        float2 m0 = make_float2(A[tid].x*SC, A[tid].y*SC);
        P[tid] = m0;
        E[tid] = make_float2(((tid % d) == i ? 1.f : 0.f) + m0.x, m0.y);
    }
    __syncthreads();
    for (int k = 2; k <= 8; ++k) {
        float2 t = make_float2(0.f, 0.f);
        if (tid < d*d) {
            int i = tid/d, j = tid%d;
            for (int u = 0; u < d; ++u)
                t = cfma(P[i*d+u], A[u*d+j], t);
            float f = SC / (float)k;
            t.x *= f; t.y *= f;
        }
        __syncthreads();
        if (tid < d*d) {
            E[tid].x += t.x; E[tid].y += t.y;
            P[tid] = t;
        }
        __syncthreads();
    }
    for (int s = 0; s < 8; ++s) {
        float2 t = make_float2(0.f, 0.f);
        if (tid < d*d) {
            int i = tid/d, j = tid%d;
            for (int u = 0; u < d; ++u)
                t = cfma(E[i*d+u], E[u*d+j], t);
        }
        __syncthreads();
        if (tid < d*d) E[tid] = t;
        __syncthreads();
    }

    if (job == 0) {
        if (tid < 100) g_S0[tid] = E[tid];
    } else if (job <= 1024) {
        if (tid < 100) g_Dm[job-1][tid] = E[tid];
    } else if (job <= 1040) {
        int q = job - 1025; int l = q/4, m = q%4;
        float vp = w[l*PW + 12 + m];
        if (tid < 100) {
            int j = tid % 10;
            float sn, cs; sincosf(vp * (float)j, &sn, &cs);
            g_sq[q][tid] = cmul(E[tid], make_float2(cs, sn));
        }
    } else if (job <= 1056) {
        int q = job - 1041; int l = q/4, m = q%4;
        float vp = w[l*PW + 32 + m];
        if (tid < 100) {
            int j = tid % 10;
            float sn, cs; sincosf(vp * (float)j, &sn, &cs);
            g_dp[q][tid] = cmul(E[tid], make_float2(cs, sn));
        }
    } else {
        if (tid < d*10) {
            int x = tid/10, t = tid%10;
            int xi = lo + x, xj = N - xi;
            float2 v = (t < d) ? E[x*d + t] : make_float2(0.f, 0.f);
            int l = g / 12, h = (g % 12) / 6, p = g % 6;
            if (t < d && h == 0 && l > 0) {
                int yi = lo + t, yj = N - yi;
                const float* kap = w + (l-1)*PW + 44;
                float ang = 0.f;
                if (p == 0)      ang = kap[0]*(float)(yi*yi) + kap[1]*(float)(yj*yj);
                else if (p == 1) ang = kap[2]*(float)(yj*yj);
                else if (p == 2) ang = kap[3]*(float)(yj*yj);
                if (ang != 0.f) {
                    float sn, cs; sincosf(ang, &sn, &cs);
                    v = cmul(v, make_float2(cs, sn));
                }
            }
            g_bs[g][xi*10 + xj][t] = v;
        }
    }
}

// ---------------------------------------------------------------------------
// Kernel 2: g_psi[b][m] = Dm[b*4+m] @ S0[:,0]
// ---------------------------------------------------------------------------
__global__ void init_psi()
{
    int t = blockIdx.x * blockDim.x + threadIdx.x;
    if (t >= BATCH*DMODES) return;
    float2 p0[CUTN];
#pragma unroll
    for (int y = 0; y < CUTN; ++y) p0[y] = g_S0[y*CUTN + 0];
    const float2* Dm = g_Dm[t];
#pragma unroll
    for (int i = 0; i < CUTN; ++i) {
        float2 acc = make_float2(0.f, 0.f);
#pragma unroll
        for (int y = 0; y < CUTN; ++y) acc = cfma(Dm[i*CUTN + y], p0[y], acc);
        g_psi[t/DMODES][t%DMODES][i] = acc;
    }
}

// ---------------------------------------------------------------------------
// Circuit kernel. Complex MAC via packed f32x2 FMA, dual accumulators to
// halve the dependent FMA chain per output row.
// ---------------------------------------------------------------------------
template<int D>
__device__ __forceinline__ void bs_item(u64* Su,
        const u64* __restrict__ Ub, const u64* __restrict__ Ubs,
        int caddr, int ds, int ur0)
{
    u64 inxx[D], inyy[D];
#pragma unroll
    for (int t = 0; t < D; ++t) {
        float2 v = ((const float2*)Su)[caddr + t*ds];
        float nvy = -v.y;
        asm("mov.b64 %0, {%1, %1};" : "=l"(inxx[t]) : "f"(v.x));
        asm("mov.b64 %0, {%1, %2};" : "=l"(inyy[t]) : "f"(nvy), "f"(v.y));
    }
#pragma unroll
    for (int x = 0; x < D; ++x) {
        u64 acca = 0ULL, accb = 0ULL;
        const u64* Ur  = Ub  + ur0 + x*90;
        const u64* Urs = Ubs + ur0 + x*90;
#pragma unroll
        for (int t = 0; t < D; ++t) {
            FMA2(acca, Ur[t],  inxx[t]);
            FMA2(accb, Urs[t], inyy[t]);
        }
        u64 acc; ADD2(acc, acca, accb);
        Su[caddr + x*ds] = acc;
    }
}

__device__ __forceinline__ void apply_bs(u64* Su, float2* Ub, float2* Ubs,
                                         int g, int p, int tid)
{
    const float2* src = &g_bs[g][0][0];
    for (int q = tid; q < 1000; q += NTHR) {
        float2 u = src[q];
        Ub[q]  = u;
        Ubs[q] = make_float2(u.y, u.x);
    }
    __syncthreads();
    const int sj = cSJ[p], sa = cSA[p], sb = cSB[p];
    const int ds = cSI[p] - cSJ[p];
    const u64* Ub64  = (const u64*)Ub;
    const u64* Ubs64 = (const u64*)Ubs;

    for (int it = tid; it < 1900; it += NTHR) {
        int N  = it / 100;
        int f  = it - N*100;
        int fa = f / 10, fb = f - fa*10;
        int base = fa*sa + fb*sb;
        int lo = (N > 9) ? N - 9 : 0;
        int hi = (N < 9) ? N : 9;
        int d  = hi - lo + 1;
        int caddr = base + N*sj + lo*ds;
        int ur0   = (9*lo + N)*10;
        switch (d) {
            case  1: bs_item< 1>(Su, Ub64, Ubs64, caddr, ds, ur0); break;
            case  2: bs_item< 2>(Su, Ub64, Ubs64, caddr, ds, ur0); break;
            case  3: bs_item< 3>(Su, Ub64, Ubs64, caddr, ds, ur0); break;
            case  4: bs_item< 4>(Su, Ub64, Ubs64, caddr, ds, ur0); break;
            case  5: bs_item< 5>(Su, Ub64, Ubs64, caddr, ds, ur0); break;
            case  6: bs_item< 6>(Su, Ub64, Ubs64, caddr, ds, ur0); break;
            case  7: bs_item< 7>(Su, Ub64, Ubs64, caddr, ds, ur0); break;
            case  8: bs_item< 8>(Su, Ub64, Ubs64, caddr, ds, ur0); break;
            case  9: bs_item< 9>(Su, Ub64, Ubs64, caddr, ds, ur0); break;
            default: bs_item<10>(Su, Ub64, Ubs64, caddr, ds, ur0); break;
        }
    }
    __syncthreads();
}

__device__ __forceinline__ void apply_single(u64* Su, float2* Ub, float2* Ubs,
                                             const float2* Ug, int m, int tid)
{
    for (int q = tid; q < 100; q += NTHR) {
        float2 u = Ug[q];
        Ub[q]  = u;
        Ubs[q] = make_float2(u.y, u.x);
    }
    __syncthreads();
    const int sm = cMS[m], r0 = cR0[m], r1 = cR1[m], r2 = cR2[m];
    const u64* Ub64  = (const u64*)Ub;
    const u64* Ubs64 = (const u64*)Ubs;

    for (int it = tid; it < 1000; it += NTHR) {
        int f0 = it / 100; int r = it - f0*100;
        int f1 = r / 10;   int f2 = r - f1*10;
        int base = f0*r0 + f1*r1 + f2*r2;
        u64 inxx[10], inyy[10];
#pragma unroll
        for (int y = 0; y < 10; ++y) {
            float2 v = ((const float2*)Su)[base + y*sm];
            float nvy = -v.y;
            asm("mov.b64 %0, {%1, %1};" : "=l"(inxx[y]) : "f"(v.x));
            asm("mov.b64 %0, {%1, %2};" : "=l"(inyy[y]) : "f"(nvy), "f"(v.y));
        }
#pragma unroll
        for (int x = 0; x < 10; ++x) {
            u64 acca = 0ULL, accb = 0ULL;
#pragma unroll
            for (int y = 0; y < 10; ++y) {
                FMA2(acca, Ub64[x*10 + y],  inxx[y]);
                FMA2(accb, Ubs64[x*10 + y], inyy[y]);
            }
            u64 acc; ADD2(acc, acca, accb);
            Su[base + x*sm] = acc;
        }
    }
    __syncthreads();
}

__global__ void __launch_bounds__(NTHR, 2)
circuit(const float* __restrict__ w, float* __restrict__ out)
{
    extern __shared__ float2 sh[];
    float2* S   = sh;                   // 11107
    float2* Ub  = sh + SSZ;             // 1000
    float2* Ubs = sh + SSZ + 1000;      // 1000
    float2* PV  = sh + SSZ + 2000;      // 40
    __shared__ float red[12*4];

    const int b = blockIdx.x, tid = threadIdx.x;
    u64* Su = (u64*)S;

    // initial product state
    if (tid < 40) PV[tid] = g_psi[b][tid/10][tid%10];
    __syncthreads();
    for (int o = tid; o < 10000; o += NTHR) {
        int i = o/1000, j = (o/100)%10, kk = (o/10)%10, l = o%10;
        S[o + i*111 + j*11 + kk] = cmul(cmul(PV[i], PV[10+j]), cmul(PV[20+kk], PV[30+l]));
    }
    __syncthreads();

    for (int lay = 0; lay < NLAYERS; ++lay) {
        for (int p = 0; p < 6; ++p) apply_bs(Su, Ub, Ubs, lay*12 + p, p, tid);
        for (int m = 0; m < 4; ++m) apply_single(Su, Ub, Ubs, g_sq[lay*4 + m], m, tid);
        for (int p = 0; p < 6; ++p) apply_bs(Su, Ub, Ubs, lay*12 + 6 + p, p, tid);
        for (int m = 0; m < 4; ++m) apply_single(Su, Ub, Ubs, g_dp[lay*4 + m], m, tid);
    }

    // <n_m> readout
    float a0 = 0.f, a1 = 0.f, a2 = 0.f, a3 = 0.f;
    for (int o = tid; o < 10000; o += NTHR) {
        int i = o/1000, j = (o/100)%10, kk = (o/10)%10, l = o%10;
        float2 s = S[o + i*111 + j*11 + kk];
        float pr = s.x*s.x + s.y*s.y;
        a0 += pr * (float)i;
        a1 += pr * (float)j;
        a2 += pr * (float)kk;
        a3 += pr * (float)l;
    }
#pragma unroll
    for (int off = 16; off > 0; off >>= 1) {
        a0 += __shfl_down_sync(0xffffffffu, a0, off);
        a1 += __shfl_down_sync(0xffffffffu, a1, off);
        a2 += __shfl_down_sync(0xffffffffu, a2, off);
        a3 += __shfl_down_sync(0xffffffffu, a3, off);
    }
    int wid = tid / 32, lane = tid % 32;
    if (lane == 0) {
        red[wid*4 + 0] = a0; red[wid*4 + 1] = a1;
        red[wid*4 + 2] = a2; red[wid*4 + 3] = a3;
    }
    __syncthreads();
    if (tid < 4) {
        float s = 0.f;
        for (int ww = 0; ww < 12; ++ww) s += red[ww*4 + tid];
        out[b*4 + tid] = s;
    }
}

// ---------------------------------------------------------------------------
#define CIRCUIT_SMEM ((SSZ + 2000 + 40) * (int)sizeof(float2))   // 105176 B

extern "C" void kernel_launch(void* const* d_in, const int* in_sizes, int n_in,
                              void* d_out, int out_size)
{
    const float* inputs  = (const float*)d_in[0];
    const float* weights = (const float*)d_in[1];
    float* out = (float*)d_out;

    cudaFuncSetAttribute(circuit, cudaFuncAttributeMaxDynamicSharedMemorySize, CIRCUIT_SMEM);

    build_gates<<<NJOBS, 128>>>(inputs, weights);
    init_psi<<<4, 256>>>();
    circuit<<<BATCH, NTHR, CIRCUIT_SMEM>>>(weights, out);
}

// round 7
// speedup vs baseline: 2.6222x; 1.2720x over previous
#include <cuda_runtime.h>
#include <math.h>

// Problem constants
#define CUTN    10
#define DMODES  4
#define BATCH   256
#define NLAYERS 4
#define PW      48
#define NBS     48
#define NSEC    19

#define NTHR    384

// Padded state strides (float2 units), all odd -> conflict-light LDS
#define S0P 1111
#define S1P 111
#define S2P 11
#define S3P 1
#define SSZ (9*S0P + 9*S1P + 9*S2P + 9*S3P + 1)   // 11107 float2

typedef unsigned long long u64;

// ---------------------------------------------------------------------------
__device__ __forceinline__ float2 cmul(float2 a, float2 b) {
    return make_float2(a.x*b.x - a.y*b.y, a.x*b.y + a.y*b.x);
}
__device__ __forceinline__ float2 cfma(float2 a, float2 b, float2 acc) {
    acc.x += a.x*b.x - a.y*b.y;
    acc.y += a.x*b.y + a.y*b.x;
    return acc;
}
__device__ __forceinline__ float2 expi(float a) {
    float s, c; sincosf(a, &s, &c);
    return make_float2(c, s);
}

#define FMA2(acc, a, b) \
    asm("fma.rn.f32x2 %0, %1, %2, %0;" : "+l"(acc) : "l"(a), "l"(b))
#define ADD2(out, a, b) \
    asm("add.rn.f32x2 %0, %1, %2;" : "=l"(out) : "l"(a), "l"(b))

// ---------------------------------------------------------------------------
// Device scratch.  All gate matrices are REAL, stored duplicated (R,R) so a
// single broadcast LDS.64 feeds FMA2 directly.
// ---------------------------------------------------------------------------
__device__ float2 g_bs[NBS][100][10];      // banded real BS gates, dup (R,R)
__device__ float2 g_sq[16][100];           // real squeeze, dup
__device__ float2 g_dp[16][100];           // real displacement magnitude part, dup
__device__ float2 g_S0[100];               // complex
__device__ float2 g_Dm[BATCH*DMODES][100]; // complex
__device__ float2 g_psi[BATCH][DMODES][CUTN];

// Pair strides: p over (0,1),(0,2),(0,3),(1,2),(1,3),(2,3)
__constant__ int cSI[6] = {S0P,S0P,S0P,S1P,S1P,S2P};
__constant__ int cSJ[6] = {S1P,S2P,S3P,S2P,S3P,S3P};
__constant__ int cSA[6] = {S2P,S1P,S1P,S0P,S0P,S0P};
__constant__ int cSB[6] = {S3P,S3P,S2P,S3P,S2P,S1P};
__constant__ int cPI[6] = {0,0,0,1,1,2};
__constant__ int cPJ[6] = {1,2,3,2,3,3};
__constant__ int cMS[4] = {S0P,S1P,S2P,S3P};
__constant__ int cR0[4] = {S1P,S0P,S0P,S0P};
__constant__ int cR1[4] = {S2P,S2P,S1P,S1P};
__constant__ int cR2[4] = {S3P,S3P,S3P,S2P};

// Weight layout per layer: th1:0 ph1:6 vp1:12 rsq:16 th2:20 ph2:26 vp2:32 rd:36 phd:40 kap:44

// ---------------------------------------------------------------------------
// Kernel 1: build all gate matrices.  BS / squeeze / displacement generators
// are REAL (phases handled at runtime via pending-phase conjugation):
//   BS:   exp(th (A - A^T)) per photon sector (banded)
//   SQ:   exp(0.5 r (a^2 - adag^2))
//   DP:   exp(rd (adag - a))
// S0 and the input displacements stay complex (used only for init).
// ---------------------------------------------------------------------------
#define NJOBS (1 + 1024 + 16 + 16 + NBS*NSEC)

__global__ void build_gates(const float* __restrict__ inputs,
                            const float* __restrict__ w)
{
    __shared__ float2 A[100], E[100], P[100];
    const int job = blockIdx.x;
    const int tid = threadIdx.x;

    int d = CUTN;
    int lo = 0, N = 0, g = 0;
    const bool isBS = (job >= 1057);
    if (isBS) {
        int idx = job - 1057;
        g = idx / NSEC;  N = idx % NSEC;
        lo = max(0, N - (CUTN-1));
        int hi = min(CUTN-1, N);
        d = hi - lo + 1;
    }

    if (tid < d*d) {
        int i = tid / d, j = tid % d;
        float2 v = make_float2(0.f, 0.f);
        if (job == 0) {
            if (i == j-2)      v = make_float2(0.f, -0.25f * sqrtf((float)(j*(j-1))));
            else if (i == j+2) v = make_float2(0.f, -0.25f * sqrtf((float)((j+1)*(j+2))));
        } else if (job <= 1024) {
            float xv = inputs[job-1];
            if (i == j+1)      v = make_float2( xv * sqrtf((float)(j+1)), 0.f);
            else if (i == j-1) v = make_float2(-xv * sqrtf((float)j),     0.f);
        } else if (job <= 1040) {
            int q = job - 1025; int l = q/4, m = q%4;
            float r = w[l*PW + 16 + m];
            if (i == j-2)      v = make_float2( 0.5f*r*sqrtf((float)(j*(j-1))),     0.f);
            else if (i == j+2) v = make_float2(-0.5f*r*sqrtf((float)((j+1)*(j+2))), 0.f);
        } else if (job <= 1056) {
            int q = job - 1041; int l = q/4, m = q%4;
            float rd = w[l*PW + 36 + m];          // magnitude only (phase via conj)
            if (i == j+1)      v = make_float2( rd * sqrtf((float)(j+1)), 0.f);
            else if (i == j-1) v = make_float2(-rd * sqrtf((float)j),     0.f);
        } else {
            int l = g / 12; int h = (g % 12) / 6; int p = g % 6;
            float th = w[l*PW + (h ? 20 : 0) + p];   // real generator, no phase
            int yi = lo + j; int yj = N - yi;
            if (i == j+1)      v = make_float2( th * sqrtf((float)((yi+1)*yj)), 0.f);
            else if (i == j-1) v = make_float2(-th * sqrtf((float)(yi*(yj+1))), 0.f);
        }
        A[tid] = v;
    }
    __syncthreads();

    const float SC = 1.0f/256.0f;
    if (tid < d*d) {
        int i = tid/d;
        float2 m0 = make_float2(A[tid].x*SC, A[tid].y*SC);
        P[tid] = m0;
        E[tid] = make_float2(((tid % d) == i ? 1.f : 0.f) + m0.x, m0.y);
    }
    __syncthreads();
    for (int k = 2; k <= 8; ++k) {
        float2 t = make_float2(0.f, 0.f);
        if (tid < d*d) {
            int i = tid/d, j = tid%d;
            for (int u = 0; u < d; ++u)
                t = cfma(P[i*d+u], A[u*d+j], t);
            float f = SC / (float)k;
            t.x *= f; t.y *= f;
        }
        __syncthreads();
        if (tid < d*d) {
            E[tid].x += t.x; E[tid].y += t.y;
            P[tid] = t;
        }
        __syncthreads();
    }
    for (int s = 0; s < 8; ++s) {
        float2 t = make_float2(0.f, 0.f);
        if (tid < d*d) {
            int i = tid/d, j = tid%d;
            for (int u = 0; u < d; ++u)
                t = cfma(E[i*d+u], E[u*d+j], t);
        }
        __syncthreads();
        if (tid < d*d) E[tid] = t;
        __syncthreads();
    }

    if (job == 0) {
        if (tid < 100) g_S0[tid] = E[tid];
    } else if (job <= 1024) {
        if (tid < 100) g_Dm[job-1][tid] = E[tid];
    } else if (job <= 1040) {
        if (tid < 100) { float r = E[tid].x; g_sq[job-1025][tid] = make_float2(r, r); }
    } else if (job <= 1056) {
        if (tid < 100) { float r = E[tid].x; g_dp[job-1041][tid] = make_float2(r, r); }
    } else {
        if (tid < d*10) {
            int x = tid/10, t = tid%10;
            int xi = lo + x, xj = N - xi;
            float r = (t < d) ? E[x*d + t].x : 0.f;
            g_bs[g][xi*10 + xj][t] = make_float2(r, r);
        }
    }
}

// ---------------------------------------------------------------------------
// Kernel 2: g_psi[b][m] = Dm[b*4+m] @ S0[:,0]
// ---------------------------------------------------------------------------
__global__ void init_psi()
{
    int t = blockIdx.x * blockDim.x + threadIdx.x;
    if (t >= BATCH*DMODES) return;
    float2 p0[CUTN];
#pragma unroll
    for (int y = 0; y < CUTN; ++y) p0[y] = g_S0[y*CUTN + 0];
    const float2* Dm = g_Dm[t];
#pragma unroll
    for (int i = 0; i < CUTN; ++i) {
        float2 acc = make_float2(0.f, 0.f);
#pragma unroll
        for (int y = 0; y < CUTN; ++y) acc = cfma(Dm[i*CUTN + y], p0[y], acc);
        g_psi[t/DMODES][t%DMODES][i] = acc;
    }
}

// ---------------------------------------------------------------------------
// Circuit kernel.  Real gates + pending-phase bookkeeping.
// Per cMAC: 1 broadcast LDS.64 of (R,R) + 1 FMA2.
// Per tap:  state load + complex phase multiply from a broadcast table.
// ---------------------------------------------------------------------------
template<int D>
__device__ __forceinline__ void bs_item_r(u64* Su, const u64* __restrict__ Ub,
        const u64* __restrict__ tab, const u64* __restrict__ tabs,
        int caddr, int ds, int ur0)
{
    u64 inp[D];
#pragma unroll
    for (int t = 0; t < D; ++t) {
        float2 v = ((const float2*)Su)[caddr + t*ds];
        float nvy = -v.y;
        u64 xx, yy;
        asm("mov.b64 %0, {%1, %1};" : "=l"(xx) : "f"(v.x));
        asm("mov.b64 %0, {%1, %2};" : "=l"(yy) : "f"(nvy), "f"(v.y));
        u64 p = 0ULL;
        FMA2(p, tab[t],  xx);
        FMA2(p, tabs[t], yy);
        inp[t] = p;
    }
#pragma unroll
    for (int x = 0; x < D; ++x) {
        const u64* Ur = Ub + ur0 + x*90;
        u64 a = 0ULL, b = 0ULL;
#pragma unroll
        for (int t = 0; t + 1 < D; t += 2) {
            FMA2(a, Ur[t],   inp[t]);
            FMA2(b, Ur[t+1], inp[t+1]);
        }
        if (D & 1) FMA2(a, Ur[D-1], inp[D-1]);
        u64 acc; ADD2(acc, a, b);
        Su[caddr + x*ds] = acc;
    }
}

__device__ __forceinline__ void apply_bs(u64* Su, u64* Ub, u64* tab, u64* tabs,
                                         float2* pend, float2* Ai, float2* Aj,
                                         int g, int p, float phi, int tid)
{
    // stage Ub + build active phase vectors from pending, then update pending
    {
        const u64* src = (const u64*)&g_bs[g][0][0];
        for (int q = tid; q < 1000; q += NTHR) Ub[q] = src[q];
    }
    const int mi = cPI[p], mj = cPJ[p];
    if (tid < 10) {
        Ai[tid] = cmul(pend[mi*10 + tid], expi(-phi * (float)tid));
    } else if (tid < 20) {
        int t = tid - 10;
        Aj[t] = pend[mj*10 + t];
    }
    __syncthreads();
    if (tid < 190) {
        int N = tid / 10, t = tid % 10;
        int lo = (N > 9) ? N - 9 : 0;
        int yi = lo + t, yj = N - yi;
        float2 val = make_float2(0.f, 0.f);
        if (yi <= 9 && yj >= 0) val = cmul(Ai[yi], Aj[yj]);
        ((float2*)tab)[tid]  = val;
        ((float2*)tabs)[tid] = make_float2(val.y, val.x);
    } else if (tid >= 256 && tid < 276) {
        int t = tid - 256;
        if (t < 10) pend[mi*10 + t] = expi(phi * (float)t);
        else        pend[mj*10 + (t-10)] = make_float2(1.f, 0.f);
    }
    __syncthreads();

    const int sj = cSJ[p], sa = cSA[p], sb = cSB[p];
    const int ds = cSI[p] - cSJ[p];

    for (int it = tid; it < 1900; it += NTHR) {
        int N  = it / 100;
        int f  = it - N*100;
        int fa = f / 10, fb = f - fa*10;
        int base = fa*sa + fb*sb;
        int lo = (N > 9) ? N - 9 : 0;
        int hi = (N < 9) ? N : 9;
        int d  = hi - lo + 1;
        int caddr = base + N*sj + lo*ds;
        int ur0   = (9*lo + N)*10;
        const u64* tN  = tab  + N*10;
        const u64* tNs = tabs + N*10;
        switch (d) {
            case  1: bs_item_r< 1>(Su, Ub, tN, tNs, caddr, ds, ur0); break;
            case  2: bs_item_r< 2>(Su, Ub, tN, tNs, caddr, ds, ur0); break;
            case  3: bs_item_r< 3>(Su, Ub, tN, tNs, caddr, ds, ur0); break;
            case  4: bs_item_r< 4>(Su, Ub, tN, tNs, caddr, ds, ur0); break;
            case  5: bs_item_r< 5>(Su, Ub, tN, tNs, caddr, ds, ur0); break;
            case  6: bs_item_r< 6>(Su, Ub, tN, tNs, caddr, ds, ur0); break;
            case  7: bs_item_r< 7>(Su, Ub, tN, tNs, caddr, ds, ur0); break;
            case  8: bs_item_r< 8>(Su, Ub, tN, tNs, caddr, ds, ur0); break;
            case  9: bs_item_r< 9>(Su, Ub, tN, tNs, caddr, ds, ur0); break;
            default: bs_item_r<10>(Su, Ub, tN, tNs, caddr, ds, ur0); break;
        }
    }
    __syncthreads();
}

// has_phi: displacement uses conjugation phase phi; squeeze passes phi=0
__device__ __forceinline__ void apply_single(u64* Su, u64* Ub, u64* tab, u64* tabs,
                                             float2* pend, const float2* Ug,
                                             int m, float phi, bool has_phi, int tid)
{
    {
        const u64* src = (const u64*)Ug;
        for (int q = tid; q < 100; q += NTHR) Ub[q] = src[q];
    }
    if (tid < 10) {
        float2 val = pend[m*10 + tid];
        if (has_phi) val = cmul(val, expi(-phi * (float)tid));
        ((float2*)tab)[tid]  = val;
        ((float2*)tabs)[tid] = make_float2(val.y, val.x);
        pend[m*10 + tid] = has_phi ? expi(phi * (float)tid) : make_float2(1.f, 0.f);
    }
    __syncthreads();

    const int sm = cMS[m], r0 = cR0[m], r1 = cR1[m], r2 = cR2[m];

    for (int it = tid; it < 1000; it += NTHR) {
        int f0 = it / 100; int r = it - f0*100;
        int f1 = r / 10;   int f2 = r - f1*10;
        int base = f0*r0 + f1*r1 + f2*r2;
        u64 inp[10];
#pragma unroll
        for (int y = 0; y < 10; ++y) {
            float2 v = ((const float2*)Su)[base + y*sm];
            float nvy = -v.y;
            u64 xx, yy;
            asm("mov.b64 %0, {%1, %1};" : "=l"(xx) : "f"(v.x));
            asm("mov.b64 %0, {%1, %2};" : "=l"(yy) : "f"(nvy), "f"(v.y));
            u64 pp = 0ULL;
            FMA2(pp, tab[y],  xx);
            FMA2(pp, tabs[y], yy);
            inp[y] = pp;
        }
#pragma unroll
        for (int x = 0; x < 10; ++x) {
            const u64* Ur = Ub + x*10;
            u64 a = 0ULL, b = 0ULL;
#pragma unroll
            for (int y = 0; y < 10; y += 2) {
                FMA2(a, Ur[y],   inp[y]);
                FMA2(b, Ur[y+1], inp[y+1]);
            }
            u64 acc; ADD2(acc, a, b);
            Su[base + x*sm] = acc;
        }
    }
    __syncthreads();
}

__global__ void __launch_bounds__(NTHR, 2)
circuit(const float* __restrict__ w, float* __restrict__ out)
{
    extern __shared__ float2 sh[];
    float2* S    = sh;                    // 11107
    float2* UbF  = sh + SSZ;              // 1000
    float2* tabF = sh + SSZ + 1000;       // 190
    float2* tbsF = sh + SSZ + 1190;       // 190
    float2* pend = sh + SSZ + 1380;       // 40
    float2* Ai   = sh + SSZ + 1420;       // 10
    float2* Aj   = sh + SSZ + 1430;       // 10
    float2* PV   = sh + SSZ + 1440;       // 40
    __shared__ float red[12*4];

    const int b = blockIdx.x, tid = threadIdx.x;
    u64* Su  = (u64*)S;
    u64* Ub  = (u64*)UbF;
    u64* tab = (u64*)tabF;
    u64* tbs = (u64*)tbsF;

    // initial product state + identity pending phases
    if (tid < 40) {
        PV[tid]   = g_psi[b][tid/10][tid%10];
        pend[tid] = make_float2(1.f, 0.f);
    }
    __syncthreads();
    for (int o = tid; o < 10000; o += NTHR) {
        int i = o/1000, j = (o/100)%10, kk = (o/10)%10, l = o%10;
        S[o + i*111 + j*11 + kk] = cmul(cmul(PV[i], PV[10+j]), cmul(PV[20+kk], PV[30+l]));
    }
    __syncthreads();

    for (int lay = 0; lay < NLAYERS; ++lay) {
        const float* wl = w + lay*PW;
        // interferometer 1 (real rotations + conj phases ph1)
        for (int p = 0; p < 6; ++p)
            apply_bs(Su, Ub, tab, tbs, pend, Ai, Aj, lay*12 + p, p, wl[6+p], tid);
        // vp1 merge into pending
        if (tid < 40) {
            int m = tid/10, n = tid%10;
            pend[tid] = cmul(pend[tid], expi(wl[12+m] * (float)n));
        }
        __syncthreads();
        // squeezes (real)
        for (int m = 0; m < 4; ++m)
            apply_single(Su, Ub, tab, tbs, pend, g_sq[lay*4 + m], m, 0.f, false, tid);
        // interferometer 2
        for (int p = 0; p < 6; ++p)
            apply_bs(Su, Ub, tab, tbs, pend, Ai, Aj, lay*12 + 6 + p, p, wl[26+p], tid);
        // vp2 merge
        if (tid < 40) {
            int m = tid/10, n = tid%10;
            pend[tid] = cmul(pend[tid], expi(wl[32+m] * (float)n));
        }
        __syncthreads();
        // displacements (real magnitude + conj phase phd)
        for (int m = 0; m < 4; ++m)
            apply_single(Su, Ub, tab, tbs, pend, g_dp[lay*4 + m], m, wl[40+m], true, tid);
        // Kerr merge
        if (tid < 40) {
            int m = tid/10, n = tid%10;
            pend[tid] = cmul(pend[tid], expi(wl[44+m] * (float)(n*n)));
        }
        __syncthreads();
    }
    // final pending phases are diagonal -> invisible to |psi|^2: dropped.

    // <n_m> readout
    float a0 = 0.f, a1 = 0.f, a2 = 0.f, a3 = 0.f;
    for (int o = tid; o < 10000; o += NTHR) {
        int i = o/1000, j = (o/100)%10, kk = (o/10)%10, l = o%10;
        float2 s = S[o + i*111 + j*11 + kk];
        float pr = s.x*s.x + s.y*s.y;
        a0 += pr * (float)i;
        a1 += pr * (float)j;
        a2 += pr * (float)kk;
        a3 += pr * (float)l;
    }
#pragma unroll
    for (int off = 16; off > 0; off >>= 1) {
        a0 += __shfl_down_sync(0xffffffffu, a0, off);
        a1 += __shfl_down_sync(0xffffffffu, a1, off);
        a2 += __shfl_down_sync(0xffffffffu, a2, off);
        a3 += __shfl_down_sync(0xffffffffu, a3, off);
    }
    int wid = tid / 32, lane = tid % 32;
    if (lane == 0) {
        red[wid*4 + 0] = a0; red[wid*4 + 1] = a1;
        red[wid*4 + 2] = a2; red[wid*4 + 3] = a3;
    }
    __syncthreads();
    if (tid < 4) {
        float s = 0.f;
        for (int ww = 0; ww < 12; ++ww) s += red[ww*4 + tid];
        out[b*4 + tid] = s;
    }
}

// ---------------------------------------------------------------------------
#define CIRCUIT_SMEM ((SSZ + 1480) * (int)sizeof(float2))   // 100,696 B

extern "C" void kernel_launch(void* const* d_in, const int* in_sizes, int n_in,
                              void* d_out, int out_size)
{
    const float* inputs  = (const float*)d_in[0];
    const float* weights = (const float*)d_in[1];
    float* out = (float*)d_out;

    cudaFuncSetAttribute(circuit, cudaFuncAttributeMaxDynamicSharedMemorySize, CIRCUIT_SMEM);

    build_gates<<<NJOBS, 128>>>(inputs, weights);
    init_psi<<<4, 256>>>();
    circuit<<<BATCH, NTHR, CIRCUIT_SMEM>>>(weights, out);
}

// round 8
// speedup vs baseline: 2.6657x; 1.0166x over previous
#include <cuda_runtime.h>
#include <math.h>

// Problem constants
#define CUTN    10
#define DMODES  4
#define BATCH   256
#define NLAYERS 4
#define PW      48
#define NBS     48
#define NSEC    19

#define NTHR    256

// Padded state strides (float2 units), all odd -> conflict-light LDS
#define S0P 1111
#define S1P 111
#define S2P 11
#define S3P 1
#define SSZ (9*S0P + 9*S1P + 9*S2P + 9*S3P + 1)   // 11107 float2

typedef unsigned long long u64;

// ---------------------------------------------------------------------------
__device__ __forceinline__ float2 cmul(float2 a, float2 b) {
    return make_float2(a.x*b.x - a.y*b.y, a.x*b.y + a.y*b.x);
}
__device__ __forceinline__ float2 cfma(float2 a, float2 b, float2 acc) {
    acc.x += a.x*b.x - a.y*b.y;
    acc.y += a.x*b.y + a.y*b.x;
    return acc;
}
__device__ __forceinline__ float2 expi(float a) {
    float s, c; sincosf(a, &s, &c);
    return make_float2(c, s);
}

#define FMA2(acc, a, b) \
    asm("fma.rn.f32x2 %0, %1, %2, %0;" : "+l"(acc) : "l"(a), "l"(b))

// ---------------------------------------------------------------------------
// Device scratch.  All gate matrices REAL, duplicated (R,R) for FMA2.
// ---------------------------------------------------------------------------
__device__ float2 g_bs[NBS][100][10];      // banded real BS gates, dup (R,R)
__device__ float2 g_sq[16][100];
__device__ float2 g_dp[16][100];
__device__ float2 g_S0[100];               // complex
__device__ float2 g_Dm[BATCH*DMODES][100]; // complex
__device__ float2 g_psi[BATCH][DMODES][CUTN];

// Pair strides: p over (0,1),(0,2),(0,3),(1,2),(1,3),(2,3)
__constant__ int cSI[6] = {S0P,S0P,S0P,S1P,S1P,S2P};
__constant__ int cSJ[6] = {S1P,S2P,S3P,S2P,S3P,S3P};
__constant__ int cSA[6] = {S2P,S1P,S1P,S0P,S0P,S0P};
__constant__ int cSB[6] = {S3P,S3P,S2P,S3P,S2P,S1P};
__constant__ int cPI[6] = {0,0,0,1,1,2};
__constant__ int cPJ[6] = {1,2,3,2,3,3};
__constant__ int cMS[4] = {S0P,S1P,S2P,S3P};
__constant__ int cR0[4] = {S1P,S0P,S0P,S0P};
__constant__ int cR1[4] = {S2P,S2P,S1P,S1P};
__constant__ int cR2[4] = {S3P,S3P,S3P,S2P};

// ---------------------------------------------------------------------------
// Kernel 1: build gates (expm, scaling 1/32 + 8-term Taylor + 5 squarings).
// Real generators; phases handled at runtime via pending-phase conjugation.
// ---------------------------------------------------------------------------
#define NJOBS (1 + 1024 + 16 + 16 + NBS*NSEC)

__global__ void build_gates(const float* __restrict__ inputs,
                            const float* __restrict__ w)
{
    __shared__ float2 A[100], E[100], P[100];
    const int job = blockIdx.x;
    const int tid = threadIdx.x;

    int d = CUTN;
    int lo = 0, N = 0, g = 0;
    const bool isBS = (job >= 1057);
    if (isBS) {
        int idx = job - 1057;
        g = idx / NSEC;  N = idx % NSEC;
        lo = max(0, N - (CUTN-1));
        int hi = min(CUTN-1, N);
        d = hi - lo + 1;
    }

    if (tid < d*d) {
        int i = tid / d, j = tid % d;
        float2 v = make_float2(0.f, 0.f);
        if (job == 0) {
            if (i == j-2)      v = make_float2(0.f, -0.25f * sqrtf((float)(j*(j-1))));
            else if (i == j+2) v = make_float2(0.f, -0.25f * sqrtf((float)((j+1)*(j+2))));
        } else if (job <= 1024) {
            float xv = inputs[job-1];
            if (i == j+1)      v = make_float2( xv * sqrtf((float)(j+1)), 0.f);
            else if (i == j-1) v = make_float2(-xv * sqrtf((float)j),     0.f);
        } else if (job <= 1040) {
            int q = job - 1025; int l = q/4, m = q%4;
            float r = w[l*PW + 16 + m];
            if (i == j-2)      v = make_float2( 0.5f*r*sqrtf((float)(j*(j-1))),     0.f);
            else if (i == j+2) v = make_float2(-0.5f*r*sqrtf((float)((j+1)*(j+2))), 0.f);
        } else if (job <= 1056) {
            int q = job - 1041; int l = q/4, m = q%4;
            float rd = w[l*PW + 36 + m];
            if (i == j+1)      v = make_float2( rd * sqrtf((float)(j+1)), 0.f);
            else if (i == j-1) v = make_float2(-rd * sqrtf((float)j),     0.f);
        } else {
            int l = g / 12; int h = (g % 12) / 6; int p = g % 6;
            float th = w[l*PW + (h ? 20 : 0) + p];
            int yi = lo + j; int yj = N - yi;
            if (i == j+1)      v = make_float2( th * sqrtf((float)((yi+1)*yj)), 0.f);
            else if (i == j-1) v = make_float2(-th * sqrtf((float)(yi*(yj+1))), 0.f);
        }
        A[tid] = v;
    }
    __syncthreads();

    const float SC = 1.0f/32.0f;
    if (tid < d*d) {
        int i = tid/d;
        float2 m0 = make_float2(A[tid].x*SC, A[tid].y*SC);
        P[tid] = m0;
        E[tid] = make_float2(((tid % d) == i ? 1.f : 0.f) + m0.x, m0.y);
    }
    __syncthreads();
    for (int k = 2; k <= 8; ++k) {
        float2 t = make_float2(0.f, 0.f);
        if (tid < d*d) {
            int i = tid/d, j = tid%d;
            for (int u = 0; u < d; ++u)
                t = cfma(P[i*d+u], A[u*d+j], t);
            float f = SC / (float)k;
            t.x *= f; t.y *= f;
        }
        __syncthreads();
        if (tid < d*d) {
            E[tid].x += t.x; E[tid].y += t.y;
            P[tid] = t;
        }
        __syncthreads();
    }
    for (int s = 0; s < 5; ++s) {
        float2 t = make_float2(0.f, 0.f);
        if (tid < d*d) {
            int i = tid/d, j = tid%d;
            for (int u = 0; u < d; ++u)
                t = cfma(E[i*d+u], E[u*d+j], t);
        }
        __syncthreads();
        if (tid < d*d) E[tid] = t;
        __syncthreads();
    }

    if (job == 0) {
        if (tid < 100) g_S0[tid] = E[tid];
    } else if (job <= 1024) {
        if (tid < 100) g_Dm[job-1][tid] = E[tid];
    } else if (job <= 1040) {
        if (tid < 100) { float r = E[tid].x; g_sq[job-1025][tid] = make_float2(r, r); }
    } else if (job <= 1056) {
        if (tid < 100) { float r = E[tid].x; g_dp[job-1041][tid] = make_float2(r, r); }
    } else {
        if (tid < d*10) {
            int x = tid/10, t = tid%10;
            int xi = lo + x, xj = N - xi;
            float r = (t < d) ? E[x*d + t].x : 0.f;
            g_bs[g][xi*10 + xj][t] = make_float2(r, r);
        }
    }
}

// ---------------------------------------------------------------------------
// Kernel 2: g_psi[b][m] = Dm[b*4+m] @ S0[:,0]
// ---------------------------------------------------------------------------
__global__ void init_psi()
{
    int t = blockIdx.x * blockDim.x + threadIdx.x;
    if (t >= BATCH*DMODES) return;
    float2 p0[CUTN];
#pragma unroll
    for (int y = 0; y < CUTN; ++y) p0[y] = g_S0[y*CUTN + 0];
    const float2* Dm = g_Dm[t];
#pragma unroll
    for (int i = 0; i < CUTN; ++i) {
        float2 acc = make_float2(0.f, 0.f);
#pragma unroll
        for (int y = 0; y < CUTN; ++y) acc = cfma(Dm[i*CUTN + y], p0[y], acc);
        g_psi[t/DMODES][t%DMODES][i] = acc;
    }
}

// ---------------------------------------------------------------------------
// Circuit kernel: real gates + pending phases; 2-fiber items so each U-row
// tap LDS feeds two FMA2; BS items balanced across warps by static weights.
// ---------------------------------------------------------------------------
template<int D>
__device__ __forceinline__ void bs_item2(u64* Su, const u64* __restrict__ Ub,
        const u64* __restrict__ tab, const u64* __restrict__ tabs,
        int caddr, int sb, int ds, int ur0)
{
    u64 inA[D], inB[D];
#pragma unroll
    for (int t = 0; t < D; ++t) {
        float2 va = ((const float2*)Su)[caddr + t*ds];
        float2 vb = ((const float2*)Su)[caddr + sb + t*ds];
        u64 xx, yy, pa, pb;
        float nay = -va.y, nby = -vb.y;
        u64 tb = tab[t], tbs = tabs[t];
        asm("mov.b64 %0, {%1, %1};" : "=l"(xx) : "f"(va.x));
        asm("mov.b64 %0, {%1, %2};" : "=l"(yy) : "f"(nay), "f"(va.y));
        pa = 0ULL; FMA2(pa, tb, xx); FMA2(pa, tbs, yy);
        asm("mov.b64 %0, {%1, %1};" : "=l"(xx) : "f"(vb.x));
        asm("mov.b64 %0, {%1, %2};" : "=l"(yy) : "f"(nby), "f"(vb.y));
        pb = 0ULL; FMA2(pb, tb, xx); FMA2(pb, tbs, yy);
        inA[t] = pa; inB[t] = pb;
    }
#pragma unroll
    for (int x = 0; x < D; ++x) {
        const u64* Ur = Ub + ur0 + x*90;
        u64 aA = 0ULL, aB = 0ULL;
#pragma unroll
        for (int t = 0; t < D; ++t) {
            u64 u = Ur[t];
            FMA2(aA, u, inA[t]);
            FMA2(aB, u, inB[t]);
        }
        Su[caddr + x*ds]      = aA;
        Su[caddr + sb + x*ds] = aB;
    }
}

__device__ __forceinline__ void apply_bs(u64* Su, u64* Ub, u64* tab, u64* tabs,
                                         float2* pend, float2* Ai, float2* Aj,
                                         const int* istart,
                                         int g, int p, float phi, int tid)
{
    {
        const u64* src = (const u64*)&g_bs[g][0][0];
        for (int q = tid; q < 1000; q += NTHR) Ub[q] = src[q];
    }
    const int mi = cPI[p], mj = cPJ[p];
    if (tid < 10) {
        Ai[tid] = cmul(pend[mi*10 + tid], expi(-phi * (float)tid));
    } else if (tid < 20) {
        int t = tid - 10;
        Aj[t] = pend[mj*10 + t];
    }
    __syncthreads();
    if (tid < 190) {
        int N = tid / 10, t = tid % 10;
        int lo = (N > 9) ? N - 9 : 0;
        int yi = lo + t, yj = N - yi;
        float2 val = make_float2(0.f, 0.f);
        if (yi <= 9 && yj >= 0) val = cmul(Ai[yi], Aj[yj]);
        ((float2*)tab)[tid]  = val;
        ((float2*)tabs)[tid] = make_float2(val.y, val.x);
    } else if (tid >= 192 && tid < 212) {
        int t = tid - 192;
        if (t < 10) pend[mi*10 + t] = expi(phi * (float)t);
        else        pend[mj*10 + (t-10)] = make_float2(1.f, 0.f);
    }
    __syncthreads();

    const int sj = cSJ[p], sa = cSA[p], sb = cSB[p];
    const int ds = cSI[p] - cSJ[p];
    const int wid = tid >> 5, lane = tid & 31;
    const int i1 = istart[wid+1];

    for (int it = istart[wid] + lane; it < i1; it += 32) {
        int N  = it / 50;
        int q  = it - N*50;
        int fa = q / 5;
        int fbp = (q - fa*5) * 2;
        int base = fa*sa + fbp*sb;
        int lo = (N > 9) ? N - 9 : 0;
        int hi = (N < 9) ? N : 9;
        int d  = hi - lo + 1;
        int caddr = base + N*sj + lo*ds;
        int ur0   = (9*lo + N)*10;
        const u64* tN  = tab  + N*10;
        const u64* tNs = tabs + N*10;
        switch (d) {
            case  1: bs_item2< 1>(Su, Ub, tN, tNs, caddr, sb, ds, ur0); break;
            case  2: bs_item2< 2>(Su, Ub, tN, tNs, caddr, sb, ds, ur0); break;
            case  3: bs_item2< 3>(Su, Ub, tN, tNs, caddr, sb, ds, ur0); break;
            case  4: bs_item2< 4>(Su, Ub, tN, tNs, caddr, sb, ds, ur0); break;
            case  5: bs_item2< 5>(Su, Ub, tN, tNs, caddr, sb, ds, ur0); break;
            case  6: bs_item2< 6>(Su, Ub, tN, tNs, caddr, sb, ds, ur0); break;
            case  7: bs_item2< 7>(Su, Ub, tN, tNs, caddr, sb, ds, ur0); break;
            case  8: bs_item2< 8>(Su, Ub, tN, tNs, caddr, sb, ds, ur0); break;
            case  9: bs_item2< 9>(Su, Ub, tN, tNs, caddr, sb, ds, ur0); break;
            default: bs_item2<10>(Su, Ub, tN, tNs, caddr, sb, ds, ur0); break;
        }
    }
    __syncthreads();
}

__device__ __forceinline__ void apply_single(u64* Su, u64* Ub, u64* tab, u64* tabs,
                                             float2* pend, const float2* Ug,
                                             int m, float phi, bool has_phi, int tid)
{
    {
        const u64* src = (const u64*)Ug;
        for (int q = tid; q < 100; q += NTHR) Ub[q] = src[q];
    }
    if (tid < 10) {
        float2 val = pend[m*10 + tid];
        if (has_phi) val = cmul(val, expi(-phi * (float)tid));
        ((float2*)tab)[tid]  = val;
        ((float2*)tabs)[tid] = make_float2(val.y, val.x);
        pend[m*10 + tid] = has_phi ? expi(phi * (float)tid) : make_float2(1.f, 0.f);
    }
    __syncthreads();

    const int sm = cMS[m], r0 = cR0[m], r1 = cR1[m], r2 = cR2[m];

    for (int it = tid; it < 500; it += NTHR) {
        int c    = it % 5;
        int rest = it / 5;
        int f1 = rest % 10, f0 = rest / 10;
        int base = f0*r0 + f1*r1 + (c*2)*r2;
        u64 inA[10], inB[10];
#pragma unroll
        for (int y = 0; y < 10; ++y) {
            float2 va = ((const float2*)Su)[base + y*sm];
            float2 vb = ((const float2*)Su)[base + r2 + y*sm];
            u64 xx, yy, pa, pb;
            float nay = -va.y, nby = -vb.y;
            u64 tb = tab[y], tbs = tabs[y];
            asm("mov.b64 %0, {%1, %1};" : "=l"(xx) : "f"(va.x));
            asm("mov.b64 %0, {%1, %2};" : "=l"(yy) : "f"(nay), "f"(va.y));
            pa = 0ULL; FMA2(pa, tb, xx); FMA2(pa, tbs, yy);
            asm("mov.b64 %0, {%1, %1};" : "=l"(xx) : "f"(vb.x));
            asm("mov.b64 %0, {%1, %2};" : "=l"(yy) : "f"(nby), "f"(vb.y));
            pb = 0ULL; FMA2(pb, tb, xx); FMA2(pb, tbs, yy);
            inA[y] = pa; inB[y] = pb;
        }
#pragma unroll
        for (int x = 0; x < 10; ++x) {
            const u64* Ur = Ub + x*10;
            u64 aA = 0ULL, aB = 0ULL;
#pragma unroll
            for (int y = 0; y < 10; ++y) {
                u64 u = Ur[y];
                FMA2(aA, u, inA[y]);
                FMA2(aB, u, inB[y]);
            }
            Su[base + x*sm]      = aA;
            Su[base + r2 + x*sm] = aB;
        }
    }
    __syncthreads();
}

__global__ void __launch_bounds__(NTHR, 2)
circuit(const float* __restrict__ w, float* __restrict__ out)
{
    extern __shared__ float2 sh[];
    float2* S    = sh;                    // 11107
    float2* UbF  = sh + SSZ;              // 1000
    float2* tabF = sh + SSZ + 1000;       // 190
    float2* tbsF = sh + SSZ + 1190;       // 190
    float2* pend = sh + SSZ + 1380;       // 40
    float2* Ai   = sh + SSZ + 1420;       // 10
    float2* Aj   = sh + SSZ + 1430;       // 10
    float2* PV   = sh + SSZ + 1440;       // 40
    __shared__ int istart[9];
    __shared__ float red[8*4];

    const int b = blockIdx.x, tid = threadIdx.x;
    u64* Su  = (u64*)S;
    u64* Ub  = (u64*)UbF;
    u64* tab = (u64*)tabF;
    u64* tbs = (u64*)tbsF;

    // balanced warp partition of the 950 2-fiber BS items (static weights)
    if (tid < 9) {
        int wn[19]; long long W = 0;
        for (int N = 0; N < 19; ++N) {
            int d = min(min(N + 1, 19 - N), 10);
            wn[N] = 50 * (2*d*d + 8*d + 10);
            W += wn[N];
        }
        long long tw = (long long)tid * W / 8;
        int N = 0; long long cum = 0;
        while (N < 18 && cum + wn[N] <= tw) { cum += wn[N]; N++; }
        int d = min(min(N + 1, 19 - N), 10);
        int k = (int)((tw - cum) / (2*d*d + 8*d + 10));
        if (k > 50) k = 50;
        istart[tid] = N*50 + k;
    }
    // initial product state + identity pending phases
    if (tid >= 16 && tid < 56) {
        int t = tid - 16;
        PV[t]   = g_psi[b][t/10][t%10];
        pend[t] = make_float2(1.f, 0.f);
    }
    __syncthreads();
    for (int o = tid; o < 10000; o += NTHR) {
        int i = o/1000, j = (o/100)%10, kk = (o/10)%10, l = o%10;
        S[o + i*111 + j*11 + kk] = cmul(cmul(PV[i], PV[10+j]), cmul(PV[20+kk], PV[30+l]));
    }
    __syncthreads();

    for (int lay = 0; lay < NLAYERS; ++lay) {
        const float* wl = w + lay*PW;
        for (int p = 0; p < 6; ++p)
            apply_bs(Su, Ub, tab, tbs, pend, Ai, Aj, istart, lay*12 + p, p, wl[6+p], tid);
        if (tid < 40) {
            int m = tid/10, n = tid%10;
            pend[tid] = cmul(pend[tid], expi(wl[12+m] * (float)n));
        }
        __syncthreads();
        for (int m = 0; m < 4; ++m)
            apply_single(Su, Ub, tab, tbs, pend, g_sq[lay*4 + m], m, 0.f, false, tid);
        for (int p = 0; p < 6; ++p)
            apply_bs(Su, Ub, tab, tbs, pend, Ai, Aj, istart, lay*12 + 6 + p, p, wl[26+p], tid);
        if (tid < 40) {
            int m = tid/10, n = tid%10;
            pend[tid] = cmul(pend[tid], expi(wl[32+m] * (float)n));
        }
        __syncthreads();
        for (int m = 0; m < 4; ++m)
            apply_single(Su, Ub, tab, tbs, pend, g_dp[lay*4 + m], m, wl[40+m], true, tid);
        if (tid < 40) {
            int m = tid/10, n = tid%10;
            pend[tid] = cmul(pend[tid], expi(wl[44+m] * (float)(n*n)));
        }
        __syncthreads();
    }
    // final pending phases are diagonal -> invisible in |psi|^2

    // <n_m> readout
    float a0 = 0.f, a1 = 0.f, a2 = 0.f, a3 = 0.f;
    for (int o = tid; o < 10000; o += NTHR) {
        int i = o/1000, j = (o/100)%10, kk = (o/10)%10, l = o%10;
        float2 s = S[o + i*111 + j*11 + kk];
        float pr = s.x*s.x + s.y*s.y;
        a0 += pr * (float)i;
        a1 += pr * (float)j;
        a2 += pr * (float)kk;
        a3 += pr * (float)l;
    }
#pragma unroll
    for (int off = 16; off > 0; off >>= 1) {
        a0 += __shfl_down_sync(0xffffffffu, a0, off);
        a1 += __shfl_down_sync(0xffffffffu, a1, off);
        a2 += __shfl_down_sync(0xffffffffu, a2, off);
        a3 += __shfl_down_sync(0xffffffffu, a3, off);
    }
    int wid = tid / 32, lane = tid % 32;
    if (lane == 0) {
        red[wid*4 + 0] = a0; red[wid*4 + 1] = a1;
        red[wid*4 + 2] = a2; red[wid*4 + 3] = a3;
    }
    __syncthreads();
    if (tid < 4) {
        float s = 0.f;
        for (int ww = 0; ww < 8; ++ww) s += red[ww*4 + tid];
        out[b*4 + tid] = s;
    }
}

// ---------------------------------------------------------------------------
#define CIRCUIT_SMEM ((SSZ + 1480) * (int)sizeof(float2))   // 100,696 B

extern "C" void kernel_launch(void* const* d_in, const int* in_sizes, int n_in,
                              void* d_out, int out_size)
{
    const float* inputs  = (const float*)d_in[0];
    const float* weights = (const float*)d_in[1];
    float* out = (float*)d_out;

    cudaFuncSetAttribute(circuit, cudaFuncAttributeMaxDynamicSharedMemorySize, CIRCUIT_SMEM);

    build_gates<<<NJOBS, 128>>>(inputs, weights);
    init_psi<<<4, 256>>>();
    circuit<<<BATCH, NTHR, CIRCUIT_SMEM>>>(weights, out);
}